// round 6
// baseline (speedup 1.0000x reference)
#include <cuda_runtime.h>
#include <cuda_fp16.h>
#include <cstdint>

#define B_   2
#define N_   2048
#define DIM_ 768
#define H_   12
#define DH_  64
#define M1   (B_*N_)     // 4096
#define NC1  (3*DIM_)    // 2304
#define KH2  768
#define PITCHB 3072      // bytes per fp16 limb row

// ---------------- device globals ----------------
__device__ uint32_t g_xl[(long)M1*KH2];      // x fp16 limbs (h,l)
__device__ uint32_t g_w1[(long)NC1*KH2];     // wqkv fp16 limbs (h,l)
__device__ uint32_t g_w2[(long)NC1*KH2];     // wqkv fp16 limbs (l,h)
__device__ float    g_bq[NC1];
// int8 pipeline
__device__ uint8_t  g_q8[(long)B_*H_*N_*128];   // [bh][n][qhi(64)|qlo(64)]
__device__ uint8_t  g_k8[(long)B_*H_*N_*128];   // [bh][m][khi|klo]
__device__ uint8_t  g_vh[(long)B_*H_*DH_*N_];   // [bh][e][m] hi bytes
__device__ uint8_t  g_vl[(long)B_*H_*DH_*N_];   // lo bytes
__device__ uint8_t  g_zh[(long)M1*DIM_];        // z hi plane [m][d]
__device__ uint8_t  g_zlo[(long)M1*DIM_];       // z lo plane
__device__ int8_t   g_wp8[(long)DIM_*DIM_];     // wp single s8 limb [e][d]
__device__ int      g_bp16[DIM_];               // bp * 256

// ---------------- scalar helpers ----------------
__device__ __forceinline__ float qround8(float x) {
    float t = __fmaf_rn(x, 256.f, 12582912.f);
    return (t - 12582912.f) * 0.00390625f;
}
__device__ __forceinline__ float q32_16(float x) {
    float t = __fmaf_rn(x, 65536.f, 12582912.f);
    return (t - 12582912.f) * 1.52587890625e-5f;
}
__device__ __forceinline__ uint32_t packu32(__half a, __half b) {
    __half2 t = __halves2half2(a, b);
    return *(uint32_t*)&t;
}
__device__ __forceinline__ int clamp16(int t) { return min(32767, max(-32768, t)); }
// round-half-even of (hi + lo/256); works for negative lo (arith shift = floor)
__device__ __forceinline__ int comb_rnd(int hi, int lo) {
    int base = hi + (lo >> 8);
    int r = lo & 255;
    if (r > 128 || (r == 128 && (base & 1))) base++;
    return base;
}

// ---------------- PTX helpers ----------------
__device__ __forceinline__ uint32_t smem_u32(const void* p) {
    uint32_t a;
    asm("{ .reg .u64 t; cvta.to.shared.u64 t, %1; cvt.u32.u64 %0, t; }" : "=r"(a) : "l"(p));
    return a;
}
#define CP_ASYNC16(dst, src) \
    asm volatile("cp.async.cg.shared.global [%0], [%1], 16;" :: "r"(dst), "l"(src) : "memory")
#define CP_COMMIT() asm volatile("cp.async.commit_group;" ::: "memory")
#define CP_WAIT(n)  asm volatile("cp.async.wait_group %0;" :: "n"(n) : "memory")

__device__ __forceinline__ void ldm_x4(uint32_t* r, uint32_t addr) {
    asm volatile("ldmatrix.sync.aligned.m8n8.x4.shared.b16 {%0,%1,%2,%3}, [%4];"
        : "=r"(r[0]), "=r"(r[1]), "=r"(r[2]), "=r"(r[3]) : "r"(addr));
}
__device__ __forceinline__ void mma16816(float* d, const uint32_t* a, const uint32_t* b) {
    asm volatile("mma.sync.aligned.m16n8k16.row.col.f32.f16.f16.f32 "
        "{%0,%1,%2,%3}, {%4,%5,%6,%7}, {%8,%9}, {%0,%1,%2,%3};"
        : "+f"(d[0]), "+f"(d[1]), "+f"(d[2]), "+f"(d[3])
        : "r"(a[0]), "r"(a[1]), "r"(a[2]), "r"(a[3]), "r"(b[0]), "r"(b[1]));
}
#define IMMA_OP(name, at, bt) \
__device__ __forceinline__ void name(int* d, const uint32_t* a, const uint32_t* b) { \
    asm volatile("mma.sync.aligned.m16n8k32.row.col.s32." at "." bt ".s32 " \
        "{%0,%1,%2,%3}, {%4,%5,%6,%7}, {%8,%9}, {%0,%1,%2,%3};" \
        : "+r"(d[0]), "+r"(d[1]), "+r"(d[2]), "+r"(d[3]) \
        : "r"(a[0]), "r"(a[1]), "r"(a[2]), "r"(a[3]), "r"(b[0]), "r"(b[1])); \
}
IMMA_OP(mma_ss, "s8", "s8")
IMMA_OP(mma_su, "s8", "u8")
IMMA_OP(mma_us, "u8", "s8")
IMMA_OP(mma_uu, "u8", "u8")

#define SWZ(row, colb) ((uint32_t)((row)*128 + ((colb) ^ (((row)&7)<<4))))
// pair-packed 64B rows into 128B pitch (conflict-free, verified phase pattern)
#define BSWZ(row, colb) ((uint32_t)(((row)>>1)*128 + (((((row)&1)<<6) | (colb)) ^ ((((row)>>1)&7)<<4))))

// ---------------- kernel 1: prep ----------------
__global__ void prep_kernel(const float* __restrict__ x, const float* __restrict__ wqkv,
                            const float* __restrict__ bqkv, const float* __restrict__ wp,
                            const float* __restrict__ bp) {
    long i = (long)blockIdx.x * blockDim.x + threadIdx.x;
    const long NX = (long)M1 * DIM_;
    const long NW = (long)NC1 * DIM_;
    const long NP = (long)DIM_ * DIM_;
    if (i < NX) {
        float v = q32_16(x[i]);
        __half h = __float2half_rn(v);
        __half l = __float2half_rn(v - __half2float(h));
        g_xl[i] = packu32(h, l);
        return;
    }
    i -= NX;
    if (i < NW) {
        float w = qround8(wqkv[i]);
        __half h = __float2half_rn(w);
        __half l = __float2half_rn(w - __half2float(h));
        g_w1[i] = packu32(h, l);
        g_w2[i] = packu32(l, h);
        return;
    }
    i -= NW;
    if (i < NP) {
        int t = __float2int_rn(wp[i] * 256.f);
        g_wp8[i] = (int8_t)min(127, max(-128, t));
        return;
    }
    i -= NP;
    if (i < NC1) { g_bq[i] = qround8(bqkv[i]); return; }
    i -= NC1;
    if (i < DIM_) g_bp16[i] = __float2int_rn(bp[i] * 256.f);
}

// ---------------- fp16 GEMM core (QKV) — unchanged from round 4 ----------------
#define GSTG 49152
struct AccTile { float a[2][8][4]; };

__device__ __forceinline__ void gemm_issue2(uint32_t st, const char* Ab, const char* B1b,
                                            const char* B2b, int kbyte, int tid) {
    #pragma unroll
    for (int i = 0; i < 4; i++) {
        int idx = tid + i * 256;
        int row = idx >> 3, c16 = (idx & 7) << 4;
        CP_ASYNC16(st + SWZ(row, c16), Ab + (long)row * PITCHB + kbyte + c16);
    }
    #pragma unroll
    for (int i = 0; i < 4; i++) {
        int idx = tid + i * 256;
        int row = idx >> 3, c16 = (idx & 7) << 4;
        CP_ASYNC16(st + 16384 + SWZ(row, c16), B1b + (long)row * PITCHB + kbyte + c16);
    }
    #pragma unroll
    for (int i = 0; i < 4; i++) {
        int idx = tid + i * 256;
        int row = idx >> 3, c16 = (idx & 7) << 4;
        CP_ASYNC16(st + 32768 + SWZ(row, c16), B2b + (long)row * PITCHB + kbyte + c16);
    }
    CP_COMMIT();
}
__device__ __forceinline__ void gemm_compute2(uint32_t st, AccTile& acc, int wm, int wn, int lane) {
    const int arow_l = (lane & 7) + ((lane >> 3) & 1) * 8;
    const int achk   = (lane >> 4) * 16;
    const int brow_l = (lane & 7) + (lane >> 4) * 8;
    const int bchk   = ((lane >> 3) & 1) * 16;
    #pragma unroll
    for (int kk = 0; kk < 4; kk++) {
        uint32_t a[2][4];
        #pragma unroll
        for (int f = 0; f < 2; f++)
            ldm_x4(a[f], st + SWZ(wm * 32 + f * 16 + arow_l, kk * 32 + achk));
        #pragma unroll
        for (int half = 0; half < 2; half++) {
            uint32_t base = st + 16384 + half * 16384;
            #pragma unroll
            for (int g = 0; g < 4; g++) {
                uint32_t b4[4];
                ldm_x4(b4, base + SWZ(wn * 64 + g * 16 + brow_l, kk * 32 + bchk));
                #pragma unroll
                for (int f = 0; f < 2; f++) {
                    mma16816(acc.a[f][g * 2 + 0], a[f], b4 + 0);
                    mma16816(acc.a[f][g * 2 + 1], a[f], b4 + 2);
                }
            }
        }
    }
}
__device__ __forceinline__ void gemm_main2(const char* Ab, const char* B1b, const char* B2b,
                                           AccTile& acc, char* smem, int tid) {
    uint32_t sb = smem_u32(smem);
    const int lane = tid & 31, wid = tid >> 5;
    const int wm = wid & 3, wn = wid >> 2;
    #pragma unroll
    for (int f = 0; f < 2; f++)
        #pragma unroll
        for (int j = 0; j < 8; j++)
            #pragma unroll
            for (int e = 0; e < 4; e++) acc.a[f][j][e] = 0.f;

    gemm_issue2(sb + 0 * GSTG, Ab, B1b, B2b, 0, tid);
    gemm_issue2(sb + 1 * GSTG, Ab, B1b, B2b, 128, tid);
    #pragma unroll 1
    for (int g = 0; g < 24; g++) {
        if (g + 2 < 24) { CP_WAIT(1); } else { CP_WAIT(0); }
        __syncthreads();
        if (g + 2 < 24)
            gemm_issue2(sb + ((g + 2) % 3) * GSTG, Ab, B1b, B2b, (g + 2) * 128, tid);
        gemm_compute2(sb + (g % 3) * GSTG, acc, wm, wn, lane);
    }
}

// ---------------- kernel 2: QKV (fp16 HMMA) → int8 plane epilogue ----------------
__global__ void __launch_bounds__(256, 1) gemm_qkv_tc() {
    extern __shared__ char smem[];
    const int tid = threadIdx.x;
    const int m0 = blockIdx.y * 128;
    const int n0 = blockIdx.x * 128;
    AccTile acc;
    gemm_main2((const char*)g_xl + (long)m0 * PITCHB,
               (const char*)g_w1 + (long)n0 * PITCHB,
               (const char*)g_w2 + (long)n0 * PITCHB, acc, smem, tid);

    const int wid = tid >> 5, lane = tid & 31;
    const int wm = wid & 3, wn = wid >> 2;
    const int rb = m0 + wm * 32 + (lane >> 2);
    const int cb = n0 + wn * 64 + (lane & 3) * 2;
    #pragma unroll
    for (int f = 0; f < 2; f++) {
        #pragma unroll
        for (int j = 0; j < 8; j++) {
            int nb = cb + j * 8;                 // even
            float b0 = g_bq[nb], b1 = g_bq[nb + 1];
            int h = nb / 192;
            int rr = nb - h * 192;
            int seg = rr >> 6, e = rr & 63;      // e even
            #pragma unroll
            for (int rs = 0; rs < 2; rs++) {
                int m = rb + f * 16 + rs * 8;
                int bi = m >> 11, nr = m & 2047;
                long bh = bi * H_ + h;
                int t0 = clamp16(__float2int_rn((acc.a[f][j][rs * 2 + 0] + b0) * 256.f));
                int t1 = clamp16(__float2int_rn((acc.a[f][j][rs * 2 + 1] + b1) * 256.f));
                uint16_t hip = (uint16_t)((uint8_t)(t0 >> 8) | ((uint16_t)(uint8_t)(t1 >> 8) << 8));
                uint16_t lop = (uint16_t)((uint8_t)t0 | ((uint16_t)(uint8_t)t1 << 8));
                if (seg == 0) {
                    long base = (bh * N_ + nr) * 128;
                    *(uint16_t*)(g_q8 + base + e) = hip;
                    *(uint16_t*)(g_q8 + base + 64 + e) = lop;
                } else if (seg == 1) {
                    long base = (bh * N_ + nr) * 128;
                    *(uint16_t*)(g_k8 + base + e) = hip;
                    *(uint16_t*)(g_k8 + base + 64 + e) = lop;
                } else {
                    long vb = (bh * DH_ + e) * N_ + nr;
                    g_vh[vb] = (uint8_t)(t0 >> 8);
                    g_vh[vb + N_] = (uint8_t)(t1 >> 8);
                    g_vl[vb] = (uint8_t)t0;
                    g_vl[vb + N_] = (uint8_t)t1;
                }
            }
        }
    }
}

// ---------------- kernel 3: int8 flash attention (exact) ----------------
#define AQ 0u
#define AK 16384u
#define AV 32768u
#define AS 49152u
#define ATTN_SMEM 65536

__device__ __forceinline__ void attn_issue(uint32_t sK, uint32_t sV,
        const uint8_t* kbp, const uint8_t* vhb, const uint8_t* vlb, int kb, int tid) {
    #pragma unroll
    for (int i = 0; i < 2; i++) {
        int idx = tid + i * 256;
        int row = idx >> 3, c = (idx & 7) << 4;
        CP_ASYNC16(sK + SWZ(row, c), kbp + (long)(kb + row) * 128 + c);
    }
    #pragma unroll
    for (int i = 0; i < 2; i++) {
        int idx = tid + i * 256;
        int row = idx >> 3, c = idx & 7;
        const uint8_t* src = (c < 4 ? vhb : vlb) + (long)row * N_ + kb + (c & 3) * 16;
        CP_ASYNC16(sV + SWZ(row, c << 4), src);
    }
    CP_COMMIT();
}

__global__ void __launch_bounds__(256, 1) attn_i8() {
    extern __shared__ char smem[];
    const uint32_t sb = smem_u32(smem);
    const int tid = threadIdx.x, lane = tid & 31, wid = tid >> 5;
    const int wm = wid & 3, wn = wid >> 2;
    const int bh = blockIdx.y, q0 = blockIdx.x * 128;
    const uint8_t* qb  = g_q8 + ((long)bh * N_ + q0) * 128;
    const uint8_t* kbp = g_k8 + (long)bh * N_ * 128;
    const uint8_t* vhb = g_vh + (long)bh * DH_ * N_;
    const uint8_t* vlb = g_vl + (long)bh * DH_ * N_;

    #pragma unroll
    for (int i = 0; i < 4; i++) {
        int idx = tid + i * 256;
        int row = idx >> 3, c = (idx & 7) << 4;
        CP_ASYNC16(sb + AQ + SWZ(row, c), qb + (long)row * 128 + c);
    }
    attn_issue(sb + AK, sb + AV, kbp, vhb, vlb, 0, tid);

    const int arow_l = (lane & 7) + ((lane >> 3) & 1) * 8;
    const int achk   = (lane >> 4) * 16;
    const int brow_l = (lane & 7) + (lane >> 4) * 8;
    const int bchk   = ((lane >> 3) & 1) * 16;
    const int qr     = lane >> 2;
    const int qc     = (lane & 3) * 2;

    int Z01[2][4][4] = {};
    int Zll[2][4][4] = {};

    #pragma unroll 1
    for (int it = 0; it < 32; it++) {
        CP_WAIT(0);
        __syncthreads();
        if (it + 1 < 32)
            attn_issue(sb + AK + (uint32_t)((it + 1) & 1) * 8192u,
                       sb + AV + (uint32_t)((it + 1) & 1) * 8192u,
                       kbp, vhb, vlb, (it + 1) * 64, tid);
        const uint32_t sK = sb + AK + (uint32_t)(it & 1) * 8192u;
        const uint32_t sV = sb + AV + (uint32_t)(it & 1) * 8192u;

        // ---- phase 1: s = q x k^T (exact) ----
        #pragma unroll
        for (int g = 0; g < 2; g++) {
            int hh[2][2][4] = {}, hl[2][2][4] = {}, ll[2][2][4] = {};
            #pragma unroll
            for (int kk = 0; kk < 2; kk++) {
                uint32_t a[2][2][4];
                #pragma unroll
                for (int ar = 0; ar < 2; ar++)
                    #pragma unroll
                    for (int f = 0; f < 2; f++)
                        ldm_x4(a[ar][f], sb + AQ + SWZ(wm * 32 + f * 16 + arow_l, ar * 64 + kk * 32 + achk));
                uint32_t bf2[2][4];
                #pragma unroll
                for (int br = 0; br < 2; br++)
                    ldm_x4(bf2[br], sK + SWZ(wn * 32 + g * 16 + brow_l, br * 64 + kk * 32 + bchk));
                #pragma unroll
                for (int f = 0; f < 2; f++) {
                    mma_ss(hh[f][0], a[0][f], bf2[0] + 0); mma_ss(hh[f][1], a[0][f], bf2[0] + 2);
                    mma_su(hl[f][0], a[0][f], bf2[1] + 0); mma_su(hl[f][1], a[0][f], bf2[1] + 2);
                    mma_us(hl[f][0], a[1][f], bf2[0] + 0); mma_us(hl[f][1], a[1][f], bf2[0] + 2);
                    mma_uu(ll[f][0], a[1][f], bf2[1] + 0); mma_uu(ll[f][1], a[1][f], bf2[1] + 2);
                }
            }
            #pragma unroll
            for (int f = 0; f < 2; f++)
                #pragma unroll
                for (int s = 0; s < 2; s++)
                    #pragma unroll
                    for (int rs = 0; rs < 2; rs++) {
                        int row = wm * 32 + f * 16 + qr + rs * 8;
                        int col = wn * 32 + g * 16 + s * 8 + qc;
                        int t0 = clamp16(comb_rnd((hh[f][s][rs*2+0] << 8) + hl[f][s][rs*2+0], ll[f][s][rs*2+0]));
                        int t1 = clamp16(comb_rnd((hh[f][s][rs*2+1] << 8) + hl[f][s][rs*2+1], ll[f][s][rs*2+1]));
                        *(uint16_t*)(smem + AS + SWZ(row, col)) =
                            (uint16_t)((uint8_t)(t0 >> 8) | ((uint16_t)(uint8_t)(t1 >> 8) << 8));
                        *(uint16_t*)(smem + AS + SWZ(row, 64 + col)) =
                            (uint16_t)((uint8_t)t0 | ((uint16_t)(uint8_t)t1 << 8));
                    }
        }
        __syncthreads();

        // ---- phase 2: z += s x v (exact) ----
        #pragma unroll
        for (int g = 0; g < 2; g++) {
            int hh[2][2][4] = {}, hl[2][2][4] = {}, ll[2][2][4] = {};
            #pragma unroll
            for (int kk = 0; kk < 2; kk++) {
                uint32_t a[2][2][4];
                #pragma unroll
                for (int ar = 0; ar < 2; ar++)
                    #pragma unroll
                    for (int f = 0; f < 2; f++)
                        ldm_x4(a[ar][f], sb + AS + SWZ(wm * 32 + f * 16 + arow_l, ar * 64 + kk * 32 + achk));
                uint32_t bf2[2][4];
                #pragma unroll
                for (int br = 0; br < 2; br++)
                    ldm_x4(bf2[br], sV + SWZ(wn * 32 + g * 16 + brow_l, br * 64 + kk * 32 + bchk));
                #pragma unroll
                for (int f = 0; f < 2; f++) {
                    mma_ss(hh[f][0], a[0][f], bf2[0] + 0); mma_ss(hh[f][1], a[0][f], bf2[0] + 2);
                    mma_su(hl[f][0], a[0][f], bf2[1] + 0); mma_su(hl[f][1], a[0][f], bf2[1] + 2);
                    mma_us(hl[f][0], a[1][f], bf2[0] + 0); mma_us(hl[f][1], a[1][f], bf2[0] + 2);
                    mma_uu(ll[f][0], a[1][f], bf2[1] + 0); mma_uu(ll[f][1], a[1][f], bf2[1] + 2);
                }
            }
            #pragma unroll
            for (int f = 0; f < 2; f++)
                #pragma unroll
                for (int s = 0; s < 2; s++)
                    #pragma unroll
                    for (int e = 0; e < 4; e++) {
                        Z01[f][g * 2 + s][e] += (hh[f][s][e] << 8) + hl[f][s][e];
                        Zll[f][g * 2 + s][e] += ll[f][s][e];
                    }
        }
    }

    // epilogue: z quantize (clamped) → byte planes
    const int b = bh / H_, h = bh - b * H_;
    #pragma unroll
    for (int f = 0; f < 2; f++)
        #pragma unroll
        for (int j = 0; j < 4; j++)
            #pragma unroll
            for (int rs = 0; rs < 2; rs++) {
                int ntok = q0 + wm * 32 + f * 16 + qr + rs * 8;
                int d = h * 64 + wn * 32 + j * 8 + qc;
                int t0 = clamp16(comb_rnd(Z01[f][j][rs * 2 + 0], Zll[f][j][rs * 2 + 0]));
                int t1 = clamp16(comb_rnd(Z01[f][j][rs * 2 + 1], Zll[f][j][rs * 2 + 1]));
                long off = (long)(b * N_ + ntok) * DIM_ + d;
                *(uint16_t*)(g_zh + off) =
                    (uint16_t)((uint8_t)(t0 >> 8) | ((uint16_t)(uint8_t)(t1 >> 8) << 8));
                *(uint16_t*)(g_zlo + off) =
                    (uint16_t)((uint8_t)t0 | ((uint16_t)(uint8_t)t1 << 8));
            }
}

// ---------------- kernel 4: int8 output projection (exact) ----------------
#define PSTG 20480   // A 16KB + B 4KB

__device__ __forceinline__ void proj_issue(uint32_t st, const uint8_t* zh, const uint8_t* zl,
                                           const uint8_t* wp, int kc, int tid) {
    #pragma unroll
    for (int i = 0; i < 4; i++) {
        int idx = tid + i * 256;
        int row = idx >> 3, p = idx & 7;
        const uint8_t* src = (p < 4 ? zh : zl) + (long)row * DIM_ + kc * 64 + (p & 3) * 16;
        CP_ASYNC16(st + SWZ(row, p << 4), src);
    }
    {
        int row = tid >> 2, c = (tid & 3) << 4;
        CP_ASYNC16(st + 16384 + BSWZ(row, c), wp + (long)row * DIM_ + kc * 64 + c);
    }
    CP_COMMIT();
}

__global__ void __launch_bounds__(256, 1) proj_i8(float* __restrict__ out) {
    extern __shared__ char smem[];
    const uint32_t sb = smem_u32(smem);
    const int tid = threadIdx.x, lane = tid & 31, wid = tid >> 5;
    const int wm = wid & 3, wn = wid >> 2;
    const int m0 = blockIdx.y * 128;
    const int n0 = blockIdx.x * 64;
    const uint8_t* zh = g_zh + (long)m0 * DIM_;
    const uint8_t* zl = g_zlo + (long)m0 * DIM_;
    const uint8_t* wp = (const uint8_t*)g_wp8 + (long)n0 * DIM_;

    const int arow_l = (lane & 7) + ((lane >> 3) & 1) * 8;
    const int achk   = (lane >> 4) * 16;
    const int brow_l = (lane & 7) + (lane >> 4) * 8;
    const int bchk   = ((lane >> 3) & 1) * 16;
    const int qr     = lane >> 2;
    const int qc     = (lane & 3) * 2;

    int C1[2][4][4] = {}, C2[2][4][4] = {};

    proj_issue(sb + 0 * PSTG, zh, zl, wp, 0, tid);
    proj_issue(sb + 1 * PSTG, zh, zl, wp, 1, tid);
    #pragma unroll 1
    for (int c = 0; c < 12; c++) {
        if (c + 2 < 12) { CP_WAIT(1); } else { CP_WAIT(0); }
        __syncthreads();
        if (c + 2 < 12)
            proj_issue(sb + ((c + 2) % 3) * PSTG, zh, zl, wp, c + 2, tid);
        uint32_t stA = sb + (c % 3) * PSTG;
        uint32_t stB = stA + 16384;
        #pragma unroll
        for (int kk = 0; kk < 2; kk++) {
            uint32_t ah[2][4], al[2][4];
            #pragma unroll
            for (int f = 0; f < 2; f++) {
                ldm_x4(ah[f], stA + SWZ(wm * 32 + f * 16 + arow_l, kk * 32 + achk));
                ldm_x4(al[f], stA + SWZ(wm * 32 + f * 16 + arow_l, 64 + kk * 32 + achk));
            }
            #pragma unroll
            for (int g = 0; g < 2; g++) {
                uint32_t bf2[4];
                ldm_x4(bf2, stB + BSWZ(wn * 32 + g * 16 + brow_l, kk * 32 + bchk));
                #pragma unroll
                for (int f = 0; f < 2; f++) {
                    mma_ss(C1[f][g * 2 + 0], ah[f], bf2 + 0);
                    mma_ss(C1[f][g * 2 + 1], ah[f], bf2 + 2);
                    mma_us(C2[f][g * 2 + 0], al[f], bf2 + 0);
                    mma_us(C2[f][g * 2 + 1], al[f], bf2 + 2);
                }
            }
        }
    }

    // epilogue: out = (bp16 + rhe(256*C1 + C2)/256... all integer, exact
    #pragma unroll
    for (int f = 0; f < 2; f++)
        #pragma unroll
        for (int j = 0; j < 4; j++)
            #pragma unroll
            for (int rs = 0; rs < 2; rs++) {
                int m = m0 + wm * 32 + f * 16 + qr + rs * 8;
                int n = n0 + wn * 32 + j * 8 + qc;
                #pragma unroll
                for (int cs = 0; cs < 2; cs++) {
                    int v = g_bp16[n + cs] + comb_rnd(C1[f][j][rs * 2 + cs], C2[f][j][rs * 2 + cs]);
                    out[(long)m * DIM_ + n + cs] = (float)v * 0.00390625f;
                }
            }
}

// ---------------- launch ----------------
extern "C" void kernel_launch(void* const* d_in, const int* in_sizes, int n_in,
                              void* d_out, int out_size) {
    const float* q_in = (const float*)d_in[0];
    const float* wqkv = (const float*)d_in[1];
    const float* bqkv = (const float*)d_in[2];
    const float* wp   = (const float*)d_in[3];
    const float* bp   = (const float*)d_in[4];
    float* out = (float*)d_out;

    const long total = (long)M1 * DIM_ + (long)NC1 * DIM_ + (long)DIM_ * DIM_ + NC1 + DIM_;
    prep_kernel<<<(unsigned)((total + 255) / 256), 256>>>(q_in, wqkv, bqkv, wp, bp);

    const int gemm_smem = 3 * GSTG;   // 147456
    cudaFuncSetAttribute(gemm_qkv_tc, cudaFuncAttributeMaxDynamicSharedMemorySize, gemm_smem);
    gemm_qkv_tc<<<dim3(NC1 / 128, M1 / 128), 256, gemm_smem>>>();     // (18, 32)

    cudaFuncSetAttribute(attn_i8, cudaFuncAttributeMaxDynamicSharedMemorySize, ATTN_SMEM);
    attn_i8<<<dim3(N_ / 128, B_ * H_), 256, ATTN_SMEM>>>();           // (16, 24)

    const int proj_smem = 3 * PSTG;   // 61440
    cudaFuncSetAttribute(proj_i8, cudaFuncAttributeMaxDynamicSharedMemorySize, proj_smem);
    proj_i8<<<dim3(DIM_ / 64, M1 / 128), 256, proj_smem>>>(out);      // (12, 32)
}

// round 7
// speedup vs baseline: 1.6842x; 1.6842x over previous
#include <cuda_runtime.h>
#include <cuda_fp16.h>
#include <cstdint>

#define B_   2
#define N_   2048
#define DIM_ 768
#define H_   12
#define DH_  64
#define M1   (B_*N_)     // 4096
#define NC1  (3*DIM_)    // 2304
#define KH2  768         // half2 limb-pairs per GEMM row
#define PITCHB 3072      // bytes per GEMM limb row

// ---------------- device globals ----------------
__device__ uint32_t g_xl[(long)M1*KH2];      // x limbs (h,l)
__device__ uint32_t g_w1[(long)NC1*KH2];     // wqkv limbs (h,l)
__device__ uint32_t g_w2[(long)NC1*KH2];     // wqkv limbs (l,h)
__device__ uint32_t g_p1[(long)DIM_*KH2];    // wp limbs
__device__ uint32_t g_p2[(long)DIM_*KH2];
__device__ uint32_t g_zl[(long)M1*KH2];      // z limbs (attention output)
__device__ uint32_t g_ql[(long)B_*H_*N_*DH_];        // q limbs [bh][n][64]
__device__ uint32_t g_k12[(long)B_*H_*N_*2*DH_];     // k limbs [bh][m][128]: (kh,kl)x64 | (kl,kh)x64
__device__ uint32_t g_vt[(long)B_*H_*DH_*N_];        // v^T limbs [bh][e][m] (vh,vl)
__device__ uint32_t g_vt2[(long)B_*H_*DH_*N_];       // swapped (vl,vh)
__device__ float    g_bq[NC1];
__device__ float    g_bp2[DIM_];

// ---------------- quantizers ----------------
__device__ __forceinline__ float qround8(float x) {        // round-half-even to 2^-8
    float t = __fmaf_rn(x, 256.f, 12582912.f);
    return (t - 12582912.f) * 0.00390625f;
}
__device__ __forceinline__ float q16_8c(float x) {         // with clamp (z saturates)
    float t = __fmaf_rn(x, 256.f, 12582912.f);
    float y = t - 12582912.f;
    y = fminf(fmaxf(y, -32768.f), 32767.f);
    return y * 0.00390625f;
}
__device__ __forceinline__ float q32_16(float x) {
    float t = __fmaf_rn(x, 65536.f, 12582912.f);
    return (t - 12582912.f) * 1.52587890625e-5f;
}
__device__ __forceinline__ uint32_t packu32(__half a, __half b) {
    __half2 t = __halves2half2(a, b);
    return *(uint32_t*)&t;
}

// ---------------- PTX helpers ----------------
__device__ __forceinline__ uint32_t smem_u32(const void* p) {
    uint32_t a;
    asm("{ .reg .u64 t; cvta.to.shared.u64 t, %1; cvt.u32.u64 %0, t; }" : "=r"(a) : "l"(p));
    return a;
}
#define CP_ASYNC16(dst, src) \
    asm volatile("cp.async.cg.shared.global [%0], [%1], 16;" :: "r"(dst), "l"(src) : "memory")
#define CP_COMMIT() asm volatile("cp.async.commit_group;" ::: "memory")
#define CP_WAIT(n)  asm volatile("cp.async.wait_group %0;" :: "n"(n) : "memory")

__device__ __forceinline__ void ldm_x4(uint32_t* r, uint32_t addr) {
    asm volatile("ldmatrix.sync.aligned.m8n8.x4.shared.b16 {%0,%1,%2,%3}, [%4];"
        : "=r"(r[0]), "=r"(r[1]), "=r"(r[2]), "=r"(r[3]) : "r"(addr));
}
__device__ __forceinline__ void mma16816(float* d, const uint32_t* a, const uint32_t* b) {
    asm volatile("mma.sync.aligned.m16n8k16.row.col.f32.f16.f16.f32 "
        "{%0,%1,%2,%3}, {%4,%5,%6,%7}, {%8,%9}, {%0,%1,%2,%3};"
        : "+f"(d[0]), "+f"(d[1]), "+f"(d[2]), "+f"(d[3])
        : "r"(a[0]), "r"(a[1]), "r"(a[2]), "r"(a[3]), "r"(b[0]), "r"(b[1]));
}

// swizzle: XOR 16B-chunk id with row%8 within a 128B group
#define SWP(pitch, row, colb) ((uint32_t)((row)*(pitch) + (((colb)) ^ (((row)&7)<<4))))
#define SWZ(row, colb) SWP(128, row, colb)

// ---------------- kernel 1: quantize + limb-split inputs ----------------
__global__ void prep_kernel(const float* __restrict__ x, const float* __restrict__ wqkv,
                            const float* __restrict__ bqkv, const float* __restrict__ wp,
                            const float* __restrict__ bp) {
    long i = (long)blockIdx.x * blockDim.x + threadIdx.x;
    const long NX = (long)M1 * DIM_;
    const long NW = (long)NC1 * DIM_;
    const long NP = (long)DIM_ * DIM_;
    if (i < NX) {
        float v = q32_16(x[i]);
        __half h = __float2half_rn(v);
        __half l = __float2half_rn(v - __half2float(h));
        g_xl[i] = packu32(h, l);
        return;
    }
    i -= NX;
    if (i < NW) {
        float w = qround8(wqkv[i]);
        __half h = __float2half_rn(w);
        __half l = __float2half_rn(w - __half2float(h));
        g_w1[i] = packu32(h, l);
        g_w2[i] = packu32(l, h);
        return;
    }
    i -= NW;
    if (i < NP) {
        float w = qround8(wp[i]);
        __half h = __float2half_rn(w);
        __half l = __float2half_rn(w - __half2float(h));
        g_p1[i] = packu32(h, l);
        g_p2[i] = packu32(l, h);
        return;
    }
    i -= NP;
    if (i < NC1) { g_bq[i] = qround8(bqkv[i]); return; }
    i -= NC1;
    if (i < DIM_) g_bp2[i] = qround8(bp[i]);
}

// ---------------- GEMM: dual-B single pass, 2-stage (96KB -> 2 CTA/SM) ----------------
#define GSTG 49152
struct AccTile { float a[2][8][4]; };

__device__ __forceinline__ void gemm_issue2(uint32_t st, const char* Ab, const char* B1b,
                                            const char* B2b, int kbyte, int tid) {
    #pragma unroll
    for (int i = 0; i < 4; i++) {
        int idx = tid + i * 256;
        int row = idx >> 3, c16 = (idx & 7) << 4;
        CP_ASYNC16(st + SWZ(row, c16), Ab + (long)row * PITCHB + kbyte + c16);
    }
    #pragma unroll
    for (int i = 0; i < 4; i++) {
        int idx = tid + i * 256;
        int row = idx >> 3, c16 = (idx & 7) << 4;
        CP_ASYNC16(st + 16384 + SWZ(row, c16), B1b + (long)row * PITCHB + kbyte + c16);
    }
    #pragma unroll
    for (int i = 0; i < 4; i++) {
        int idx = tid + i * 256;
        int row = idx >> 3, c16 = (idx & 7) << 4;
        CP_ASYNC16(st + 32768 + SWZ(row, c16), B2b + (long)row * PITCHB + kbyte + c16);
    }
    CP_COMMIT();
}

__device__ __forceinline__ void gemm_compute2(uint32_t st, AccTile& acc, int wm, int wn, int lane) {
    const int arow_l = (lane & 7) + ((lane >> 3) & 1) * 8;
    const int achk   = (lane >> 4) * 16;
    const int brow_l = (lane & 7) + (lane >> 4) * 8;
    const int bchk   = ((lane >> 3) & 1) * 16;
    #pragma unroll
    for (int kk = 0; kk < 4; kk++) {
        uint32_t a[2][4];
        #pragma unroll
        for (int f = 0; f < 2; f++)
            ldm_x4(a[f], st + SWZ(wm * 32 + f * 16 + arow_l, kk * 32 + achk));
        #pragma unroll
        for (int half = 0; half < 2; half++) {
            uint32_t base = st + 16384 + half * 16384;
            #pragma unroll
            for (int g = 0; g < 4; g++) {
                uint32_t b4[4];
                ldm_x4(b4, base + SWZ(wn * 64 + g * 16 + brow_l, kk * 32 + bchk));
                #pragma unroll
                for (int f = 0; f < 2; f++) {
                    mma16816(acc.a[f][g * 2 + 0], a[f], b4 + 0);
                    mma16816(acc.a[f][g * 2 + 1], a[f], b4 + 2);
                }
            }
        }
    }
}

__device__ __forceinline__ void gemm_main2(const char* Ab, const char* B1b, const char* B2b,
                                           AccTile& acc, char* smem, int tid) {
    uint32_t sb = smem_u32(smem);
    const int lane = tid & 31, wid = tid >> 5;
    const int wm = wid & 3, wn = wid >> 2;
    #pragma unroll
    for (int f = 0; f < 2; f++)
        #pragma unroll
        for (int j = 0; j < 8; j++)
            #pragma unroll
            for (int e = 0; e < 4; e++) acc.a[f][j][e] = 0.f;

    gemm_issue2(sb, Ab, B1b, B2b, 0, tid);
    #pragma unroll 1
    for (int g = 0; g < 24; g++) {
        if (g + 1 < 24) {
            gemm_issue2(sb + (uint32_t)((g + 1) & 1) * GSTG, Ab, B1b, B2b, (g + 1) * 128, tid);
            CP_WAIT(1);
        } else {
            CP_WAIT(0);
        }
        __syncthreads();
        gemm_compute2(sb + (uint32_t)(g & 1) * GSTG, acc, wm, wn, lane);
        __syncthreads();   // all warps done reading buf g&1 before it is re-issued
    }
}

// ---------------- kernel 2: QKV projection (HMMA) + attention-layout epilogue ----------------
__global__ void __launch_bounds__(256, 2) gemm_qkv_tc() {
    extern __shared__ char smem[];
    const int tid = threadIdx.x;
    const int m0 = blockIdx.y * 128;
    const int n0 = blockIdx.x * 128;
    AccTile acc;
    gemm_main2((const char*)g_xl + (long)m0 * PITCHB,
               (const char*)g_w1 + (long)n0 * PITCHB,
               (const char*)g_w2 + (long)n0 * PITCHB, acc, smem, tid);

    const int wid = tid >> 5, lane = tid & 31;
    const int wm = wid & 3, wn = wid >> 2;
    const int rb = m0 + wm * 32 + (lane >> 2);
    const int cb = n0 + wn * 64 + (lane & 3) * 2;
    #pragma unroll
    for (int f = 0; f < 2; f++) {
        #pragma unroll
        for (int j = 0; j < 8; j++) {
            #pragma unroll
            for (int cs = 0; cs < 2; cs++) {
                int n = cb + j * 8 + cs;
                float bias = g_bq[n];
                int h = n / 192;
                int rr = n - h * 192;
                int seg = rr >> 6, e = rr & 63;
                #pragma unroll
                for (int rs = 0; rs < 2; rs++) {
                    int m = rb + f * 16 + rs * 8;
                    int bi = m >> 11, nr = m & 2047;
                    long bh = bi * H_ + h;
                    float v = qround8(acc.a[f][j][rs * 2 + cs] + bias);
                    __half hh = __float2half_rn(v);
                    __half ll = __float2half_rn(v - __half2float(hh));
                    if (seg == 0) {
                        g_ql[(bh * N_ + nr) * DH_ + e] = packu32(hh, ll);
                    } else if (seg == 1) {
                        long base = (bh * N_ + nr) * (2 * DH_);
                        g_k12[base + e]       = packu32(hh, ll);
                        g_k12[base + DH_ + e] = packu32(ll, hh);
                    } else {
                        long base = (bh * DH_ + e) * N_ + nr;
                        g_vt[base]  = packu32(hh, ll);
                        g_vt2[base] = packu32(ll, hh);
                    }
                }
            }
        }
    }
}

// ---------------- kernel 4: output projection (HMMA) ----------------
__global__ void __launch_bounds__(256, 2) gemm_proj_tc(float* __restrict__ out) {
    extern __shared__ char smem[];
    const int tid = threadIdx.x;
    const int m0 = blockIdx.y * 128;
    const int n0 = blockIdx.x * 128;
    AccTile acc;
    gemm_main2((const char*)g_zl + (long)m0 * PITCHB,
               (const char*)g_p1 + (long)n0 * PITCHB,
               (const char*)g_p2 + (long)n0 * PITCHB, acc, smem, tid);

    const int wid = tid >> 5, lane = tid & 31;
    const int wm = wid & 3, wn = wid >> 2;
    const int rb = m0 + wm * 32 + (lane >> 2);
    const int cb = n0 + wn * 64 + (lane & 3) * 2;
    #pragma unroll
    for (int f = 0; f < 2; f++) {
        #pragma unroll
        for (int j = 0; j < 8; j++) {
            #pragma unroll
            for (int cs = 0; cs < 2; cs++) {
                int n = cb + j * 8 + cs;
                float bias = g_bp2[n];
                #pragma unroll
                for (int rs = 0; rs < 2; rs++) {
                    int m = rb + f * 16 + rs * 8;
                    out[(long)m * DIM_ + n] = qround8(acc.a[f][j][rs * 2 + cs] + bias);
                }
            }
        }
    }
}

// ---------------- kernel 3: HMMA limb flash-attention, 32-row k-tiles (112KB) ----------------
// smem: Q [128x256B]=32K | K 2 stages [32x512B]=2x16K | V 2 stages [2bufs x 64x128B]=2x16K | S [128x128B]=16K
#define AOQ  0u
#define AOK  32768u
#define AOV  65536u
#define AOS  98304u
#define ATTN_SMEM 114688

__device__ __forceinline__ void attn_issue_kv(uint32_t sK_st, uint32_t sV_st,
        const char* kbase, const char* v0base, const char* v1base, int kb, int tid) {
    #pragma unroll
    for (int i = 0; i < 4; i++) {
        int idx = tid + i * 256;
        int row = idx >> 5, c16 = (idx & 31) << 4;
        CP_ASYNC16(sK_st + SWP(512, row, c16), kbase + (long)(kb + row) * 512 + c16);
    }
    #pragma unroll
    for (int i = 0; i < 4; i++) {
        int idx = tid + i * 256;
        int buf = idx >> 9;
        int row = (idx >> 3) & 63;
        int c16 = (idx & 7) << 4;
        const char* vb = buf ? v1base : v0base;
        CP_ASYNC16(sV_st + buf * 8192 + SWP(128, row, c16),
                   vb + (long)row * (N_ * 4) + kb * 4 + c16);
    }
    CP_COMMIT();
}

__global__ void __launch_bounds__(256, 2) attn_tc_kernel() {
    extern __shared__ char smem[];
    const uint32_t sb = smem_u32(smem);
    const int tid = threadIdx.x;
    const int lane = tid & 31, wid = tid >> 5;
    const int wm = wid & 3, wn = wid >> 2;      // wm: 4 m-groups of 32; wn: 2 n-groups
    const int bh = blockIdx.y;
    const int q0 = blockIdx.x * 128;

    const char* qbase  = (const char*)(g_ql  + (long)bh * N_ * DH_) + (long)q0 * 256;
    const char* kbase  = (const char*)(g_k12 + (long)bh * N_ * 2 * DH_);
    const char* v0base = (const char*)(g_vt  + (long)bh * DH_ * N_);
    const char* v1base = (const char*)(g_vt2 + (long)bh * DH_ * N_);

    // prologue: Q tile + first K/V stage
    #pragma unroll
    for (int i = 0; i < 8; i++) {
        int idx = tid + i * 256;
        int row = idx >> 4, c16 = (idx & 15) << 4;
        CP_ASYNC16(sb + AOQ + SWP(256, row, c16), qbase + (long)row * 256 + c16);
    }
    attn_issue_kv(sb + AOK, sb + AOV, kbase, v0base, v1base, 0, tid);

    const int arow_l = (lane & 7) + ((lane >> 3) & 1) * 8;
    const int achk   = (lane >> 4) * 16;
    const int brow_l = (lane & 7) + (lane >> 4) * 8;
    const int bchk   = ((lane >> 3) & 1) * 16;
    const int qr     = lane >> 2;
    const int qc     = (lane & 3) * 2;

    float zacc[2][4][4];
    #pragma unroll
    for (int f = 0; f < 2; f++)
        #pragma unroll
        for (int j = 0; j < 4; j++)
            #pragma unroll
            for (int e = 0; e < 4; e++) zacc[f][j][e] = 0.f;

    #pragma unroll 1
    for (int it = 0; it < 64; it++) {
        const uint32_t sK = sb + AOK + (uint32_t)(it & 1) * 16384u;
        const uint32_t sV = sb + AOV + (uint32_t)(it & 1) * 16384u;
        CP_WAIT(0);
        __syncthreads();
        if (it + 1 < 64)
            attn_issue_kv(sb + AOK + (uint32_t)((it + 1) & 1) * 16384u,
                          sb + AOV + (uint32_t)((it + 1) & 1) * 16384u,
                          kbase, v0base, v1base, (it + 1) * 32, tid);

        // ---- phase 1: s[128x32] = q x k^T (K = 256 limb-halves; diag+cross in k12 row) ----
        float sacc[2][2][4];
        #pragma unroll
        for (int f = 0; f < 2; f++)
            #pragma unroll
            for (int s = 0; s < 2; s++)
                #pragma unroll
                for (int e = 0; e < 4; e++) sacc[f][s][e] = 0.f;
        #pragma unroll
        for (int kk = 0; kk < 16; kk++) {
            int aoff = (kk & 7) * 32;
            uint32_t a[2][4];
            #pragma unroll
            for (int f = 0; f < 2; f++)
                ldm_x4(a[f], sb + AOQ + SWP(256, wm * 32 + f * 16 + arow_l, aoff + achk));
            uint32_t b4[4];
            ldm_x4(b4, sK + SWP(512, wn * 16 + brow_l, kk * 32 + bchk));
            #pragma unroll
            for (int f = 0; f < 2; f++) {
                mma16816(sacc[f][0], a[f], b4 + 0);
                mma16816(sacc[f][1], a[f], b4 + 2);
            }
        }
        // quantize s, split limbs, store (sh,sl) into S tile (pitch 128B)
        #pragma unroll
        for (int f = 0; f < 2; f++) {
            #pragma unroll
            for (int s = 0; s < 2; s++) {
                #pragma unroll
                for (int rs = 0; rs < 2; rs++) {
                    #pragma unroll
                    for (int cs = 0; cs < 2; cs++) {
                        int row = wm * 32 + f * 16 + qr + rs * 8;
                        int col = wn * 16 + s * 8 + qc + cs;
                        float sq = qround8(sacc[f][s][rs * 2 + cs]);
                        __half hh = __float2half_rn(sq);
                        __half ll = __float2half_rn(sq - __half2float(hh));
                        *(uint32_t*)(smem + AOS + (uint32_t)(row * 128 + ((col * 4) ^ ((row & 7) << 4)))) =
                            packu32(hh, ll);
                    }
                }
            }
        }
        __syncthreads();

        // ---- phase 2: z += s x v (K = 64 limb-halves; both v buffers) ----
        #pragma unroll
        for (int kk = 0; kk < 4; kk++) {
            uint32_t a[2][4];
            #pragma unroll
            for (int f = 0; f < 2; f++)
                ldm_x4(a[f], sb + AOS + SWZ(wm * 32 + f * 16 + arow_l, kk * 32 + achk));
            #pragma unroll
            for (int buf = 0; buf < 2; buf++) {
                uint32_t base = sV + buf * 8192;
                #pragma unroll
                for (int g = 0; g < 2; g++) {
                    uint32_t b4[4];
                    ldm_x4(b4, base + SWZ(wn * 32 + g * 16 + brow_l, kk * 32 + bchk));
                    #pragma unroll
                    for (int f = 0; f < 2; f++) {
                        mma16816(zacc[f][g * 2 + 0], a[f], b4 + 0);
                        mma16816(zacc[f][g * 2 + 1], a[f], b4 + 2);
                    }
                }
            }
        }
    }

    // epilogue: quantize z (clamped), limb-split, write zc layout for proj GEMM
    const int b = bh / H_, h = bh - b * H_;
    #pragma unroll
    for (int f = 0; f < 2; f++) {
        #pragma unroll
        for (int jn = 0; jn < 4; jn++) {
            #pragma unroll
            for (int rs = 0; rs < 2; rs++) {
                #pragma unroll
                for (int cs = 0; cs < 2; cs++) {
                    int n = q0 + wm * 32 + f * 16 + qr + rs * 8;
                    int e = wn * 32 + jn * 8 + qc + cs;
                    float zq = q16_8c(zacc[f][jn][rs * 2 + cs]);
                    __half hh = __float2half_rn(zq);
                    __half ll = __float2half_rn(zq - __half2float(hh));
                    g_zl[((long)(b * N_ + n)) * KH2 + h * DH_ + e] = packu32(hh, ll);
                }
            }
        }
    }
}

// ---------------- launch ----------------
extern "C" void kernel_launch(void* const* d_in, const int* in_sizes, int n_in,
                              void* d_out, int out_size) {
    const float* q_in = (const float*)d_in[0];
    const float* wqkv = (const float*)d_in[1];
    const float* bqkv = (const float*)d_in[2];
    const float* wp   = (const float*)d_in[3];
    const float* bp   = (const float*)d_in[4];
    float* out = (float*)d_out;

    const long total = (long)M1 * DIM_ + (long)NC1 * DIM_ + (long)DIM_ * DIM_ + NC1 + DIM_;
    prep_kernel<<<(unsigned)((total + 255) / 256), 256>>>(q_in, wqkv, bqkv, wp, bp);

    const int gemm_smem = 2 * GSTG;   // 98304 -> 2 CTA/SM
    cudaFuncSetAttribute(gemm_qkv_tc, cudaFuncAttributeMaxDynamicSharedMemorySize, gemm_smem);
    gemm_qkv_tc<<<dim3(NC1 / 128, M1 / 128), 256, gemm_smem>>>();       // (18, 32)

    cudaFuncSetAttribute(attn_tc_kernel, cudaFuncAttributeMaxDynamicSharedMemorySize, ATTN_SMEM);
    attn_tc_kernel<<<dim3(N_ / 128, B_ * H_), 256, ATTN_SMEM>>>();      // (16, 24)

    cudaFuncSetAttribute(gemm_proj_tc, cudaFuncAttributeMaxDynamicSharedMemorySize, gemm_smem);
    gemm_proj_tc<<<dim3(DIM_ / 128, M1 / 128), 256, gemm_smem>>>(out);  // (6, 32)
}

// round 9
// speedup vs baseline: 2.7028x; 1.6049x over previous
#include <cuda_runtime.h>
#include <cuda_fp16.h>
#include <cstdint>

#define B_   2
#define N_   2048
#define DIM_ 768
#define H_   12
#define DH_  64
#define M1   (B_*N_)     // 4096
#define NC1  (3*DIM_)    // 2304
#define KH2  768         // u32 (pair) count per GEMM row
#define PITCHB 3072      // bytes per GEMM row

// ---------------- device globals ----------------
__device__ uint32_t g_xl[(long)M1*KH2];      // x limbs interleaved (h,l)
__device__ uint32_t g_wd[(long)NC1*KH2];     // wqkv dup pairs (w,w)
__device__ uint32_t g_pd[(long)DIM_*KH2];    // wp dup pairs (w,w)
__device__ uint32_t g_zl[(long)M1*KH2];      // z limbs interleaved (attention out)
__device__ __half   g_qh[(long)B_*H_*N_*DH_];   // q single-limb [bh][n][64]
__device__ __half   g_kh[(long)B_*H_*N_*DH_];   // k single-limb [bh][m][64]
__device__ __half   g_vt[(long)B_*H_*DH_*N_];   // v^T single-limb [bh][e][m]
__device__ float    g_bq[NC1];
__device__ float    g_bp2[DIM_];

// ---------------- quantizers ----------------
__device__ __forceinline__ float qround8(float x) {        // round-half-even to 2^-8
    float t = __fmaf_rn(x, 256.f, 12582912.f);
    return (t - 12582912.f) * 0.00390625f;
}
__device__ __forceinline__ float q16_8c(float x) {         // with clamp (z saturates)
    float t = __fmaf_rn(x, 256.f, 12582912.f);
    float y = t - 12582912.f;
    y = fminf(fmaxf(y, -32768.f), 32767.f);
    return y * 0.00390625f;
}
__device__ __forceinline__ float q32_16(float x) {
    float t = __fmaf_rn(x, 65536.f, 12582912.f);
    return (t - 12582912.f) * 1.52587890625e-5f;
}
__device__ __forceinline__ uint32_t packu32(__half a, __half b) {
    __half2 t = __halves2half2(a, b);
    return *(uint32_t*)&t;
}

// ---------------- PTX helpers ----------------
__device__ __forceinline__ uint32_t smem_u32(const void* p) {
    uint32_t a;
    asm("{ .reg .u64 t; cvta.to.shared.u64 t, %1; cvt.u32.u64 %0, t; }" : "=r"(a) : "l"(p));
    return a;
}
#define CP_ASYNC16(dst, src) \
    asm volatile("cp.async.cg.shared.global [%0], [%1], 16;" :: "r"(dst), "l"(src) : "memory")
#define CP_COMMIT() asm volatile("cp.async.commit_group;" ::: "memory")
#define CP_WAIT(n)  asm volatile("cp.async.wait_group %0;" :: "n"(n) : "memory")

__device__ __forceinline__ void ldm_x4(uint32_t* r, uint32_t addr) {
    asm volatile("ldmatrix.sync.aligned.m8n8.x4.shared.b16 {%0,%1,%2,%3}, [%4];"
        : "=r"(r[0]), "=r"(r[1]), "=r"(r[2]), "=r"(r[3]) : "r"(addr));
}
__device__ __forceinline__ void mma16816(float* d, const uint32_t* a, const uint32_t* b) {
    asm volatile("mma.sync.aligned.m16n8k16.row.col.f32.f16.f16.f32 "
        "{%0,%1,%2,%3}, {%4,%5,%6,%7}, {%8,%9}, {%0,%1,%2,%3};"
        : "+f"(d[0]), "+f"(d[1]), "+f"(d[2]), "+f"(d[3])
        : "r"(a[0]), "r"(a[1]), "r"(a[2]), "r"(a[3]), "r"(b[0]), "r"(b[1]));
}

// 128B-pitch swizzle: XOR 16B-chunk id with row%8
#define SWZ(row, colb) ((uint32_t)((row)*128 + ((colb) ^ (((row)&7)<<4))))

// ---------------- kernel 1: quantize + limb-split inputs ----------------
__global__ void prep_kernel(const float* __restrict__ x, const float* __restrict__ wqkv,
                            const float* __restrict__ bqkv, const float* __restrict__ wp,
                            const float* __restrict__ bp) {
    long i = (long)blockIdx.x * blockDim.x + threadIdx.x;
    const long NX = (long)M1 * DIM_;
    const long NW = (long)NC1 * DIM_;
    const long NP = (long)DIM_ * DIM_;
    if (i < NX) {
        float v = q32_16(x[i]);
        __half h = __float2half_rn(v);
        __half l = __float2half_rn(v - __half2float(h));
        g_xl[i] = packu32(h, l);
        return;
    }
    i -= NX;
    if (i < NW) {
        __half h = __float2half_rn(qround8(wqkv[i]));   // exact: |w*256| << 2048
        g_wd[i] = packu32(h, h);
        return;
    }
    i -= NW;
    if (i < NP) {
        __half h = __float2half_rn(qround8(wp[i]));
        g_pd[i] = packu32(h, h);
        return;
    }
    i -= NP;
    if (i < NC1) { g_bq[i] = qround8(bqkv[i]); return; }
    i -= NC1;
    if (i < DIM_) g_bp2[i] = qround8(bp[i]);
}

// ---------------- GEMM core: A interleaved limbs x B dup pairs, K'=1536 halves ----------------
#define GSTG 32768   // A 16KB + B 16KB
struct AccTile { float a[2][8][4]; };

__device__ __forceinline__ void gemm_issue(uint32_t st, const char* Ab, const char* Bb,
                                           int kbyte, int tid) {
    #pragma unroll
    for (int i = 0; i < 4; i++) {
        int idx = tid + i * 256;
        int row = idx >> 3, c16 = (idx & 7) << 4;
        CP_ASYNC16(st + SWZ(row, c16), Ab + (long)row * PITCHB + kbyte + c16);
    }
    #pragma unroll
    for (int i = 0; i < 4; i++) {
        int idx = tid + i * 256;
        int row = idx >> 3, c16 = (idx & 7) << 4;
        CP_ASYNC16(st + 16384 + SWZ(row, c16), Bb + (long)row * PITCHB + kbyte + c16);
    }
    CP_COMMIT();
}

__device__ __forceinline__ void gemm_compute(uint32_t st, AccTile& acc, int wm, int wn, int lane) {
    const int arow_l = (lane & 7) + ((lane >> 3) & 1) * 8;
    const int achk   = (lane >> 4) * 16;
    const int brow_l = (lane & 7) + (lane >> 4) * 8;
    const int bchk   = ((lane >> 3) & 1) * 16;
    #pragma unroll
    for (int kk = 0; kk < 4; kk++) {
        uint32_t a[2][4];
        #pragma unroll
        for (int f = 0; f < 2; f++)
            ldm_x4(a[f], st + SWZ(wm * 32 + f * 16 + arow_l, kk * 32 + achk));
        #pragma unroll
        for (int g = 0; g < 4; g++) {
            uint32_t b4[4];
            ldm_x4(b4, st + 16384 + SWZ(wn * 64 + g * 16 + brow_l, kk * 32 + bchk));
            #pragma unroll
            for (int f = 0; f < 2; f++) {
                mma16816(acc.a[f][g * 2 + 0], a[f], b4 + 0);
                mma16816(acc.a[f][g * 2 + 1], a[f], b4 + 2);
            }
        }
    }
}

__device__ __forceinline__ void gemm_main(const char* Ab, const char* Bb,
                                          AccTile& acc, char* smem, int tid) {
    uint32_t sb = smem_u32(smem);
    const int lane = tid & 31, wid = tid >> 5;
    const int wm = wid & 3, wn = wid >> 2;
    #pragma unroll
    for (int f = 0; f < 2; f++)
        #pragma unroll
        for (int j = 0; j < 8; j++)
            #pragma unroll
            for (int e = 0; e < 4; e++) acc.a[f][j][e] = 0.f;

    gemm_issue(sb, Ab, Bb, 0, tid);
    #pragma unroll 1
    for (int g = 0; g < 24; g++) {
        if (g + 1 < 24) {
            gemm_issue(sb + (uint32_t)((g + 1) & 1) * GSTG, Ab, Bb, (g + 1) * 128, tid);
            CP_WAIT(1);
        } else {
            CP_WAIT(0);
        }
        __syncthreads();
        gemm_compute(sb + (uint32_t)(g & 1) * GSTG, acc, wm, wn, lane);
        __syncthreads();
    }
}

// ---------------- kernel 2: QKV projection + single-limb q/k/v epilogue ----------------
__global__ void __launch_bounds__(256, 2) gemm_qkv_tc() {
    extern __shared__ char smem[];
    const int tid = threadIdx.x;
    const int m0 = blockIdx.y * 128;
    const int n0 = blockIdx.x * 128;
    AccTile acc;
    gemm_main((const char*)g_xl + (long)m0 * PITCHB,
              (const char*)g_wd + (long)n0 * PITCHB, acc, smem, tid);

    const int wid = tid >> 5, lane = tid & 31;
    const int wm = wid & 3, wn = wid >> 2;
    const int rb = m0 + wm * 32 + (lane >> 2);
    const int cb = n0 + wn * 64 + (lane & 3) * 2;
    #pragma unroll
    for (int f = 0; f < 2; f++) {
        #pragma unroll
        for (int j = 0; j < 8; j++) {
            int nb = cb + j * 8;                 // even
            float b0 = g_bq[nb], b1 = g_bq[nb + 1];
            int h = nb / 192;
            int rr = nb - h * 192;
            int seg = rr >> 6, e = rr & 63;      // e even
            #pragma unroll
            for (int rs = 0; rs < 2; rs++) {
                int m = rb + f * 16 + rs * 8;
                int bi = m >> 11, nr = m & 2047;
                long bh = bi * H_ + h;
                __half h0 = __float2half_rn(qround8(acc.a[f][j][rs * 2 + 0] + b0));
                __half h1 = __float2half_rn(qround8(acc.a[f][j][rs * 2 + 1] + b1));
                if (seg == 0) {
                    *(uint32_t*)(g_qh + (bh * N_ + nr) * DH_ + e) = packu32(h0, h1);
                } else if (seg == 1) {
                    *(uint32_t*)(g_kh + (bh * N_ + nr) * DH_ + e) = packu32(h0, h1);
                } else {
                    g_vt[(bh * DH_ + e) * N_ + nr] = h0;
                    g_vt[(bh * DH_ + e + 1) * N_ + nr] = h1;
                }
            }
        }
    }
}

// ---------------- kernel 4: output projection ----------------
__global__ void __launch_bounds__(256, 2) gemm_proj_tc(float* __restrict__ out) {
    extern __shared__ char smem[];
    const int tid = threadIdx.x;
    const int m0 = blockIdx.y * 128;
    const int n0 = blockIdx.x * 128;
    AccTile acc;
    gemm_main((const char*)g_zl + (long)m0 * PITCHB,
              (const char*)g_pd + (long)n0 * PITCHB, acc, smem, tid);

    const int wid = tid >> 5, lane = tid & 31;
    const int wm = wid & 3, wn = wid >> 2;
    const int rb = m0 + wm * 32 + (lane >> 2);
    const int cb = n0 + wn * 64 + (lane & 3) * 2;
    #pragma unroll
    for (int f = 0; f < 2; f++) {
        #pragma unroll
        for (int j = 0; j < 8; j++) {
            #pragma unroll
            for (int cs = 0; cs < 2; cs++) {
                int n = cb + j * 8 + cs;
                float bias = g_bp2[n];
                #pragma unroll
                for (int rs = 0; rs < 2; rs++) {
                    int m = rb + f * 16 + rs * 8;
                    out[(long)m * DIM_ + n] = qround8(acc.a[f][j][rs * 2 + cs] + bias);
                }
            }
        }
    }
}

// ---------------- kernel 3: single-limb flash attention (80KB -> 2 CTA/SM) ----------------
// smem: Q [128][64h]=16K | K 2st [64][64h]=2x8K | V 2st [64e][64m]=2x8K | Sh 16K | Sl 16K
#define AQ   0u
#define AK   16384u
#define AV   32768u
#define ASH  49152u
#define ASL  65536u
#define ATTN_SMEM 81920

__device__ __forceinline__ void attn_issue(uint32_t sK, uint32_t sV,
        const char* khb, const char* vtb, int kb, int tid) {
    #pragma unroll
    for (int i = 0; i < 2; i++) {
        int idx = tid + i * 256;
        int row = idx >> 3, c16 = (idx & 7) << 4;
        CP_ASYNC16(sK + SWZ(row, c16), khb + (long)(kb + row) * 128 + c16);
    }
    #pragma unroll
    for (int i = 0; i < 2; i++) {
        int idx = tid + i * 256;
        int row = idx >> 3, c16 = (idx & 7) << 4;
        CP_ASYNC16(sV + SWZ(row, c16), vtb + (long)row * (N_ * 2) + kb * 2 + c16);
    }
    CP_COMMIT();
}

__global__ void __launch_bounds__(256, 2) attn_tc_kernel() {
    extern __shared__ char smem[];
    const uint32_t sb = smem_u32(smem);
    const int tid = threadIdx.x;
    const int lane = tid & 31, wid = tid >> 5;
    const int wm = wid & 3, wn = wid >> 2;   // wm: q-row group of 32; wn: col group
    const int bh = blockIdx.y;
    const int q0 = blockIdx.x * 128;

    const char* qhb = (const char*)(g_qh + ((long)bh * N_ + q0) * DH_);
    const char* khb = (const char*)(g_kh + (long)bh * N_ * DH_);
    const char* vtb = (const char*)(g_vt + (long)bh * DH_ * N_);

    // prologue: Q tile + first K/V stage
    #pragma unroll
    for (int i = 0; i < 4; i++) {
        int idx = tid + i * 256;
        int row = idx >> 3, c16 = (idx & 7) << 4;
        CP_ASYNC16(sb + AQ + SWZ(row, c16), qhb + (long)row * 128 + c16);
    }
    attn_issue(sb + AK, sb + AV, khb, vtb, 0, tid);

    const int arow_l = (lane & 7) + ((lane >> 3) & 1) * 8;
    const int achk   = (lane >> 4) * 16;
    const int brow_l = (lane & 7) + (lane >> 4) * 8;
    const int bchk   = ((lane >> 3) & 1) * 16;
    const int qr     = lane >> 2;
    const int qc     = (lane & 3) * 2;

    float zacc[2][4][4];
    #pragma unroll
    for (int f = 0; f < 2; f++)
        #pragma unroll
        for (int j = 0; j < 4; j++)
            #pragma unroll
            for (int e = 0; e < 4; e++) zacc[f][j][e] = 0.f;

    #pragma unroll 1
    for (int it = 0; it < 32; it++) {
        const uint32_t sK = sb + AK + (uint32_t)(it & 1) * 8192u;
        const uint32_t sV = sb + AV + (uint32_t)(it & 1) * 8192u;
        CP_WAIT(0);
        __syncthreads();
        if (it + 1 < 32)
            attn_issue(sb + AK + (uint32_t)((it + 1) & 1) * 8192u,
                       sb + AV + (uint32_t)((it + 1) & 1) * 8192u,
                       khb, vtb, (it + 1) * 64, tid);

        // ---- phase 1: s[128 x 64] = q x k^T, K'=64 halves = 128B -> kk<4 ----
        float sacc[2][4][4];
        #pragma unroll
        for (int f = 0; f < 2; f++)
            #pragma unroll
            for (int j = 0; j < 4; j++)
                #pragma unroll
                for (int e = 0; e < 4; e++) sacc[f][j][e] = 0.f;
        #pragma unroll
        for (int kk = 0; kk < 4; kk++) {
            uint32_t a[2][4];
            #pragma unroll
            for (int f = 0; f < 2; f++)
                ldm_x4(a[f], sb + AQ + SWZ(wm * 32 + f * 16 + arow_l, kk * 32 + achk));
            #pragma unroll
            for (int g = 0; g < 2; g++) {
                uint32_t b4[4];
                ldm_x4(b4, sK + SWZ(wn * 32 + g * 16 + brow_l, kk * 32 + bchk));
                #pragma unroll
                for (int f = 0; f < 2; f++) {
                    mma16816(sacc[f][g * 2 + 0], a[f], b4 + 0);
                    mma16816(sacc[f][g * 2 + 1], a[f], b4 + 2);
                }
            }
        }
        // quantize s -> 2 fp16 limb planes
        #pragma unroll
        for (int f = 0; f < 2; f++)
            #pragma unroll
            for (int j = 0; j < 4; j++)
                #pragma unroll
                for (int rs = 0; rs < 2; rs++)
                    #pragma unroll
                    for (int cs = 0; cs < 2; cs++) {
                        int row = wm * 32 + f * 16 + qr + rs * 8;
                        int col = wn * 32 + j * 8 + qc + cs;
                        float sq = qround8(sacc[f][j][rs * 2 + cs]);
                        __half hh = __float2half_rn(sq);
                        __half ll = __float2half_rn(sq - __half2float(hh));
                        *(__half*)(smem + ASH + SWZ(row, col * 2)) = hh;
                        *(__half*)(smem + ASL + SWZ(row, col * 2)) = ll;
                    }
        __syncthreads();

        // ---- phase 2: z += s x v, 2 planes, K'=64 m-halves = 128B -> kk<4 ----
        #pragma unroll
        for (int plane = 0; plane < 2; plane++) {
            uint32_t sp = sb + (plane ? ASL : ASH);
            #pragma unroll
            for (int kk = 0; kk < 4; kk++) {
                uint32_t a[2][4];
                #pragma unroll
                for (int f = 0; f < 2; f++)
                    ldm_x4(a[f], sp + SWZ(wm * 32 + f * 16 + arow_l, kk * 32 + achk));
                #pragma unroll
                for (int g = 0; g < 2; g++) {
                    uint32_t b4[4];
                    ldm_x4(b4, sV + SWZ(wn * 32 + g * 16 + brow_l, kk * 32 + bchk));
                    #pragma unroll
                    for (int f = 0; f < 2; f++) {
                        mma16816(zacc[f][g * 2 + 0], a[f], b4 + 0);
                        mma16816(zacc[f][g * 2 + 1], a[f], b4 + 2);
                    }
                }
            }
        }
    }

    // epilogue: quantize z (clamped), limb-split, interleaved layout for proj
    const int b = bh / H_, h = bh - b * H_;
    #pragma unroll
    for (int f = 0; f < 2; f++)
        #pragma unroll
        for (int j = 0; j < 4; j++)
            #pragma unroll
            for (int rs = 0; rs < 2; rs++)
                #pragma unroll
                for (int cs = 0; cs < 2; cs++) {
                    int n = q0 + wm * 32 + f * 16 + qr + rs * 8;
                    int e = wn * 32 + j * 8 + qc + cs;
                    float zq = q16_8c(zacc[f][j][rs * 2 + cs]);
                    __half hh = __float2half_rn(zq);
                    __half ll = __float2half_rn(zq - __half2float(hh));
                    g_zl[((long)(b * N_ + n)) * KH2 + h * DH_ + e] = packu32(hh, ll);
                }
}

// ---------------- launch ----------------
extern "C" void kernel_launch(void* const* d_in, const int* in_sizes, int n_in,
                              void* d_out, int out_size) {
    const float* q_in = (const float*)d_in[0];
    const float* wqkv = (const float*)d_in[1];
    const float* bqkv = (const float*)d_in[2];
    const float* wp   = (const float*)d_in[3];
    const float* bp   = (const float*)d_in[4];
    float* out = (float*)d_out;

    const long total = (long)M1 * DIM_ + (long)NC1 * DIM_ + (long)DIM_ * DIM_ + NC1 + DIM_;
    prep_kernel<<<(unsigned)((total + 255) / 256), 256>>>(q_in, wqkv, bqkv, wp, bp);

    const int gemm_smem = 2 * GSTG;   // 65536 -> 2 CTA/SM
    cudaFuncSetAttribute(gemm_qkv_tc, cudaFuncAttributeMaxDynamicSharedMemorySize, gemm_smem);
    gemm_qkv_tc<<<dim3(NC1 / 128, M1 / 128), 256, gemm_smem>>>();       // (18, 32)

    cudaFuncSetAttribute(attn_tc_kernel, cudaFuncAttributeMaxDynamicSharedMemorySize, ATTN_SMEM);
    attn_tc_kernel<<<dim3(N_ / 128, B_ * H_), 256, ATTN_SMEM>>>();      // (16, 24)

    cudaFuncSetAttribute(gemm_proj_tc, cudaFuncAttributeMaxDynamicSharedMemorySize, gemm_smem);
    gemm_proj_tc<<<dim3(DIM_ / 128, M1 / 128), 256, gemm_smem>>>(out);  // (6, 32)
}

// round 10
// speedup vs baseline: 4.1485x; 1.5349x over previous
#include <cuda_runtime.h>
#include <cuda_fp16.h>
#include <cstdint>

#define B_   2
#define N_   2048
#define DIM_ 768
#define H_   12
#define DH_  64
#define M1   (B_*N_)     // 4096
#define NC1  (3*DIM_)    // 2304
#define KH2  768         // u32 (pair) count per GEMM row
#define PITCHB 3072      // bytes per GEMM row

// ---------------- device globals ----------------
__device__ uint32_t g_xl[(long)M1*KH2];      // x limbs interleaved (h,l)
__device__ uint32_t g_wd[(long)NC1*KH2];     // wqkv dup pairs (w,w)
__device__ uint32_t g_pd[(long)DIM_*KH2];    // wp dup pairs (w,w)
__device__ uint32_t g_zl[(long)M1*KH2];      // z limbs interleaved (attention out)
__device__ __half   g_qh[(long)B_*H_*N_*DH_];   // q single-limb [bh][n][64]
__device__ __half   g_kh[(long)B_*H_*N_*DH_];   // k single-limb [bh][m][64]
__device__ __half   g_vt[(long)B_*H_*DH_*N_];   // v^T single-limb [bh][e][m]
__device__ float    g_bq[NC1];
__device__ float    g_bp2[DIM_];

// ---------------- quantizers ----------------
__device__ __forceinline__ float qround8(float x) {        // round-half-even to 2^-8
    float t = __fmaf_rn(x, 256.f, 12582912.f);
    return (t - 12582912.f) * 0.00390625f;
}
__device__ __forceinline__ float q16_8c(float x) {         // with clamp (z saturates)
    float t = __fmaf_rn(x, 256.f, 12582912.f);
    float y = t - 12582912.f;
    y = fminf(fmaxf(y, -32768.f), 32767.f);
    return y * 0.00390625f;
}
__device__ __forceinline__ float q32_16(float x) {
    float t = __fmaf_rn(x, 65536.f, 12582912.f);
    return (t - 12582912.f) * 1.52587890625e-5f;
}
__device__ __forceinline__ uint32_t packu32(__half a, __half b) {
    __half2 t = __halves2half2(a, b);
    return *(uint32_t*)&t;
}

// ---------------- PTX helpers ----------------
__device__ __forceinline__ uint32_t smem_u32(const void* p) {
    uint32_t a;
    asm("{ .reg .u64 t; cvta.to.shared.u64 t, %1; cvt.u32.u64 %0, t; }" : "=r"(a) : "l"(p));
    return a;
}
#define CP_ASYNC16(dst, src) \
    asm volatile("cp.async.cg.shared.global [%0], [%1], 16;" :: "r"(dst), "l"(src) : "memory")
#define CP_COMMIT() asm volatile("cp.async.commit_group;" ::: "memory")
#define CP_WAIT(n)  asm volatile("cp.async.wait_group %0;" :: "n"(n) : "memory")

__device__ __forceinline__ void ldm_x4(uint32_t* r, uint32_t addr) {
    asm volatile("ldmatrix.sync.aligned.m8n8.x4.shared.b16 {%0,%1,%2,%3}, [%4];"
        : "=r"(r[0]), "=r"(r[1]), "=r"(r[2]), "=r"(r[3]) : "r"(addr));
}
__device__ __forceinline__ void mma16816(float* d, const uint32_t* a, const uint32_t* b) {
    asm volatile("mma.sync.aligned.m16n8k16.row.col.f32.f16.f16.f32 "
        "{%0,%1,%2,%3}, {%4,%5,%6,%7}, {%8,%9}, {%0,%1,%2,%3};"
        : "+f"(d[0]), "+f"(d[1]), "+f"(d[2]), "+f"(d[3])
        : "r"(a[0]), "r"(a[1]), "r"(a[2]), "r"(a[3]), "r"(b[0]), "r"(b[1]));
}

// 128B-pitch swizzle: XOR 16B-chunk id with row%8
#define SWZ(row, colb) ((uint32_t)((row)*128 + ((colb) ^ (((row)&7)<<4))))

// ---------------- kernel 1: quantize + limb-split inputs ----------------
__global__ void prep_kernel(const float* __restrict__ x, const float* __restrict__ wqkv,
                            const float* __restrict__ bqkv, const float* __restrict__ wp,
                            const float* __restrict__ bp) {
    long i = (long)blockIdx.x * blockDim.x + threadIdx.x;
    const long NX = (long)M1 * DIM_;
    const long NW = (long)NC1 * DIM_;
    const long NP = (long)DIM_ * DIM_;
    if (i < NX) {
        float v = q32_16(x[i]);
        __half h = __float2half_rn(v);
        __half l = __float2half_rn(v - __half2float(h));
        g_xl[i] = packu32(h, l);
        return;
    }
    i -= NX;
    if (i < NW) {
        __half h = __float2half_rn(qround8(wqkv[i]));   // exact: |w*256| << 2048
        g_wd[i] = packu32(h, h);
        return;
    }
    i -= NW;
    if (i < NP) {
        __half h = __float2half_rn(qround8(wp[i]));
        g_pd[i] = packu32(h, h);
        return;
    }
    i -= NP;
    if (i < NC1) { g_bq[i] = qround8(bqkv[i]); return; }
    i -= NC1;
    if (i < DIM_) g_bp2[i] = qround8(bp[i]);
}

// ---------------- GEMM core: 3-stage single-sync multistage ----------------
#define GSTG 32768   // A 16KB + B 16KB per stage
struct AccTile { float a[2][8][4]; };

__device__ __forceinline__ void gemm_issue(uint32_t st, const char* Ab, const char* Bb,
                                           int kbyte, int tid) {
    #pragma unroll
    for (int i = 0; i < 4; i++) {
        int idx = tid + i * 256;
        int row = idx >> 3, c16 = (idx & 7) << 4;
        CP_ASYNC16(st + SWZ(row, c16), Ab + (long)row * PITCHB + kbyte + c16);
    }
    #pragma unroll
    for (int i = 0; i < 4; i++) {
        int idx = tid + i * 256;
        int row = idx >> 3, c16 = (idx & 7) << 4;
        CP_ASYNC16(st + 16384 + SWZ(row, c16), Bb + (long)row * PITCHB + kbyte + c16);
    }
    CP_COMMIT();
}

__device__ __forceinline__ void gemm_compute(uint32_t st, AccTile& acc, int wm, int wn, int lane) {
    const int arow_l = (lane & 7) + ((lane >> 3) & 1) * 8;
    const int achk   = (lane >> 4) * 16;
    const int brow_l = (lane & 7) + (lane >> 4) * 8;
    const int bchk   = ((lane >> 3) & 1) * 16;
    #pragma unroll
    for (int kk = 0; kk < 4; kk++) {
        uint32_t a[2][4];
        #pragma unroll
        for (int f = 0; f < 2; f++)
            ldm_x4(a[f], st + SWZ(wm * 32 + f * 16 + arow_l, kk * 32 + achk));
        #pragma unroll
        for (int g = 0; g < 4; g++) {
            uint32_t b4[4];
            ldm_x4(b4, st + 16384 + SWZ(wn * 64 + g * 16 + brow_l, kk * 32 + bchk));
            #pragma unroll
            for (int f = 0; f < 2; f++) {
                mma16816(acc.a[f][g * 2 + 0], a[f], b4 + 0);
                mma16816(acc.a[f][g * 2 + 1], a[f], b4 + 2);
            }
        }
    }
}

__device__ __forceinline__ void gemm_main(const char* Ab, const char* Bb,
                                          AccTile& acc, char* smem, int tid) {
    uint32_t sb = smem_u32(smem);
    const int lane = tid & 31, wid = tid >> 5;
    const int wm = wid & 3, wn = wid >> 2;
    #pragma unroll
    for (int f = 0; f < 2; f++)
        #pragma unroll
        for (int j = 0; j < 8; j++)
            #pragma unroll
            for (int e = 0; e < 4; e++) acc.a[f][j][e] = 0.f;

    gemm_issue(sb + 0 * GSTG, Ab, Bb, 0, tid);
    gemm_issue(sb + 1 * GSTG, Ab, Bb, 128, tid);
    #pragma unroll 1
    for (int g = 0; g < 24; g++) {
        if (g + 2 < 24) { CP_WAIT(1); } else { CP_WAIT(0); }
        __syncthreads();      // stage g ready; all warps done with stage g-1
        if (g + 2 < 24)
            gemm_issue(sb + (uint32_t)((g + 2) % 3) * GSTG, Ab, Bb, (g + 2) * 128, tid);
        gemm_compute(sb + (uint32_t)(g % 3) * GSTG, acc, wm, wn, lane);
    }
}

// ---------------- kernel 2: QKV projection + single-limb q/k/v epilogue ----------------
__global__ void __launch_bounds__(256, 2) gemm_qkv_tc() {
    extern __shared__ char smem[];
    const int tid = threadIdx.x;
    const int m0 = blockIdx.y * 128;
    const int n0 = blockIdx.x * 128;
    AccTile acc;
    gemm_main((const char*)g_xl + (long)m0 * PITCHB,
              (const char*)g_wd + (long)n0 * PITCHB, acc, smem, tid);

    const int wid = tid >> 5, lane = tid & 31;
    const int wm = wid & 3, wn = wid >> 2;
    const int rb = m0 + wm * 32 + (lane >> 2);
    const int cb = n0 + wn * 64 + (lane & 3) * 2;
    #pragma unroll
    for (int f = 0; f < 2; f++) {
        #pragma unroll
        for (int j = 0; j < 8; j++) {
            int nb = cb + j * 8;                 // even
            float b0 = g_bq[nb], b1 = g_bq[nb + 1];
            int h = nb / 192;
            int rr = nb - h * 192;
            int seg = rr >> 6, e = rr & 63;      // e even
            #pragma unroll
            for (int rs = 0; rs < 2; rs++) {
                int m = rb + f * 16 + rs * 8;
                int bi = m >> 11, nr = m & 2047;
                long bh = bi * H_ + h;
                __half h0 = __float2half_rn(qround8(acc.a[f][j][rs * 2 + 0] + b0));
                __half h1 = __float2half_rn(qround8(acc.a[f][j][rs * 2 + 1] + b1));
                if (seg == 0) {
                    *(uint32_t*)(g_qh + (bh * N_ + nr) * DH_ + e) = packu32(h0, h1);
                } else if (seg == 1) {
                    *(uint32_t*)(g_kh + (bh * N_ + nr) * DH_ + e) = packu32(h0, h1);
                } else {
                    g_vt[(bh * DH_ + e) * N_ + nr] = h0;
                    g_vt[(bh * DH_ + e + 1) * N_ + nr] = h1;
                }
            }
        }
    }
}

// ---------------- kernel 4: output projection ----------------
__global__ void __launch_bounds__(256, 2) gemm_proj_tc(float* __restrict__ out) {
    extern __shared__ char smem[];
    const int tid = threadIdx.x;
    const int m0 = blockIdx.y * 128;
    const int n0 = blockIdx.x * 128;
    AccTile acc;
    gemm_main((const char*)g_zl + (long)m0 * PITCHB,
              (const char*)g_pd + (long)n0 * PITCHB, acc, smem, tid);

    const int wid = tid >> 5, lane = tid & 31;
    const int wm = wid & 3, wn = wid >> 2;
    const int rb = m0 + wm * 32 + (lane >> 2);
    const int cb = n0 + wn * 64 + (lane & 3) * 2;
    #pragma unroll
    for (int f = 0; f < 2; f++) {
        #pragma unroll
        for (int j = 0; j < 8; j++) {
            #pragma unroll
            for (int cs = 0; cs < 2; cs++) {
                int n = cb + j * 8 + cs;
                float bias = g_bp2[n];
                #pragma unroll
                for (int rs = 0; rs < 2; rs++) {
                    int m = rb + f * 16 + rs * 8;
                    out[(long)m * DIM_ + n] = qround8(acc.a[f][j][rs * 2 + cs] + bias);
                }
            }
        }
    }
}

// ---------------- kernel 3: single-limb flash attention, 3-stage KV ring ----------------
// smem: Q [128][64h]=16K | KV 3 stages x (K 8K + V 8K)=48K | Sh 16K | Sl 16K  = 96KB
#define AQ    0u
#define AKV   16384u
#define ASTG  16384u
#define ASH   65536u
#define ASL   81920u
#define ATTN_SMEM 98304

__device__ __forceinline__ void attn_issue(uint32_t stage_base,
        const char* khb, const char* vtb, int kb, int tid) {
    #pragma unroll
    for (int i = 0; i < 2; i++) {
        int idx = tid + i * 256;
        int row = idx >> 3, c16 = (idx & 7) << 4;
        CP_ASYNC16(stage_base + SWZ(row, c16), khb + (long)(kb + row) * 128 + c16);
    }
    #pragma unroll
    for (int i = 0; i < 2; i++) {
        int idx = tid + i * 256;
        int row = idx >> 3, c16 = (idx & 7) << 4;
        CP_ASYNC16(stage_base + 8192 + SWZ(row, c16), vtb + (long)row * (N_ * 2) + kb * 2 + c16);
    }
    CP_COMMIT();
}

__global__ void __launch_bounds__(256, 2) attn_tc_kernel() {
    extern __shared__ char smem[];
    const uint32_t sb = smem_u32(smem);
    const int tid = threadIdx.x;
    const int lane = tid & 31, wid = tid >> 5;
    const int wm = wid & 3, wn = wid >> 2;   // wm: q-row group of 32; wn: col group
    const int bh = blockIdx.y;
    const int q0 = blockIdx.x * 128;

    const char* qhb = (const char*)(g_qh + ((long)bh * N_ + q0) * DH_);
    const char* khb = (const char*)(g_kh + (long)bh * N_ * DH_);
    const char* vtb = (const char*)(g_vt + (long)bh * DH_ * N_);

    // prologue: Q tile (folded into group 0) + stages 0,1
    #pragma unroll
    for (int i = 0; i < 4; i++) {
        int idx = tid + i * 256;
        int row = idx >> 3, c16 = (idx & 7) << 4;
        CP_ASYNC16(sb + AQ + SWZ(row, c16), qhb + (long)row * 128 + c16);
    }
    attn_issue(sb + AKV + 0 * ASTG, khb, vtb, 0, tid);
    attn_issue(sb + AKV + 1 * ASTG, khb, vtb, 64, tid);

    const int arow_l = (lane & 7) + ((lane >> 3) & 1) * 8;
    const int achk   = (lane >> 4) * 16;
    const int brow_l = (lane & 7) + (lane >> 4) * 8;
    const int bchk   = ((lane >> 3) & 1) * 16;
    const int qr     = lane >> 2;
    const int qc     = (lane & 3) * 2;

    float zacc[2][4][4];
    #pragma unroll
    for (int f = 0; f < 2; f++)
        #pragma unroll
        for (int j = 0; j < 4; j++)
            #pragma unroll
            for (int e = 0; e < 4; e++) zacc[f][j][e] = 0.f;

    #pragma unroll 1
    for (int it = 0; it < 32; it++) {
        if (it + 2 < 32) { CP_WAIT(1); } else { CP_WAIT(0); }
        __syncthreads();    // stage it ready; all warps done with stage it-1
        if (it + 2 < 32)
            attn_issue(sb + AKV + (uint32_t)((it + 2) % 3) * ASTG, khb, vtb, (it + 2) * 64, tid);
        const uint32_t sK = sb + AKV + (uint32_t)(it % 3) * ASTG;
        const uint32_t sV = sK + 8192u;

        // ---- phase 1: s[128 x 64] = q x k^T, K'=64 halves = 128B -> kk<4 ----
        float sacc[2][4][4];
        #pragma unroll
        for (int f = 0; f < 2; f++)
            #pragma unroll
            for (int j = 0; j < 4; j++)
                #pragma unroll
                for (int e = 0; e < 4; e++) sacc[f][j][e] = 0.f;
        #pragma unroll
        for (int kk = 0; kk < 4; kk++) {
            uint32_t a[2][4];
            #pragma unroll
            for (int f = 0; f < 2; f++)
                ldm_x4(a[f], sb + AQ + SWZ(wm * 32 + f * 16 + arow_l, kk * 32 + achk));
            #pragma unroll
            for (int g = 0; g < 2; g++) {
                uint32_t b4[4];
                ldm_x4(b4, sK + SWZ(wn * 32 + g * 16 + brow_l, kk * 32 + bchk));
                #pragma unroll
                for (int f = 0; f < 2; f++) {
                    mma16816(sacc[f][g * 2 + 0], a[f], b4 + 0);
                    mma16816(sacc[f][g * 2 + 1], a[f], b4 + 2);
                }
            }
        }
        // quantize s -> 2 fp16 limb planes
        #pragma unroll
        for (int f = 0; f < 2; f++)
            #pragma unroll
            for (int j = 0; j < 4; j++)
                #pragma unroll
                for (int rs = 0; rs < 2; rs++)
                    #pragma unroll
                    for (int cs = 0; cs < 2; cs++) {
                        int row = wm * 32 + f * 16 + qr + rs * 8;
                        int col = wn * 32 + j * 8 + qc + cs;
                        float sq = qround8(sacc[f][j][rs * 2 + cs]);
                        __half hh = __float2half_rn(sq);
                        __half ll = __float2half_rn(sq - __half2float(hh));
                        *(__half*)(smem + ASH + SWZ(row, col * 2)) = hh;
                        *(__half*)(smem + ASL + SWZ(row, col * 2)) = ll;
                    }
        __syncthreads();

        // ---- phase 2: z += s x v, 2 planes, K'=64 m-halves = 128B -> kk<4 ----
        #pragma unroll
        for (int plane = 0; plane < 2; plane++) {
            uint32_t sp = sb + (plane ? ASL : ASH);
            #pragma unroll
            for (int kk = 0; kk < 4; kk++) {
                uint32_t a[2][4];
                #pragma unroll
                for (int f = 0; f < 2; f++)
                    ldm_x4(a[f], sp + SWZ(wm * 32 + f * 16 + arow_l, kk * 32 + achk));
                #pragma unroll
                for (int g = 0; g < 2; g++) {
                    uint32_t b4[4];
                    ldm_x4(b4, sV + SWZ(wn * 32 + g * 16 + brow_l, kk * 32 + bchk));
                    #pragma unroll
                    for (int f = 0; f < 2; f++) {
                        mma16816(zacc[f][g * 2 + 0], a[f], b4 + 0);
                        mma16816(zacc[f][g * 2 + 1], a[f], b4 + 2);
                    }
                }
            }
        }
    }

    // epilogue: quantize z (clamped), limb-split, interleaved layout for proj
    const int b = bh / H_, h = bh - b * H_;
    #pragma unroll
    for (int f = 0; f < 2; f++)
        #pragma unroll
        for (int j = 0; j < 4; j++)
            #pragma unroll
            for (int rs = 0; rs < 2; rs++)
                #pragma unroll
                for (int cs = 0; cs < 2; cs++) {
                    int n = q0 + wm * 32 + f * 16 + qr + rs * 8;
                    int e = wn * 32 + j * 8 + qc + cs;
                    float zq = q16_8c(zacc[f][j][rs * 2 + cs]);
                    __half hh = __float2half_rn(zq);
                    __half ll = __float2half_rn(zq - __half2float(hh));
                    g_zl[((long)(b * N_ + n)) * KH2 + h * DH_ + e] = packu32(hh, ll);
                }
}

// ---------------- launch ----------------
extern "C" void kernel_launch(void* const* d_in, const int* in_sizes, int n_in,
                              void* d_out, int out_size) {
    const float* q_in = (const float*)d_in[0];
    const float* wqkv = (const float*)d_in[1];
    const float* bqkv = (const float*)d_in[2];
    const float* wp   = (const float*)d_in[3];
    const float* bp   = (const float*)d_in[4];
    float* out = (float*)d_out;

    const long total = (long)M1 * DIM_ + (long)NC1 * DIM_ + (long)DIM_ * DIM_ + NC1 + DIM_;
    prep_kernel<<<(unsigned)((total + 255) / 256), 256>>>(q_in, wqkv, bqkv, wp, bp);

    const int gemm_smem = 3 * GSTG;   // 98304 -> 2 CTA/SM
    cudaFuncSetAttribute(gemm_qkv_tc, cudaFuncAttributeMaxDynamicSharedMemorySize, gemm_smem);
    gemm_qkv_tc<<<dim3(NC1 / 128, M1 / 128), 256, gemm_smem>>>();       // (18, 32)

    cudaFuncSetAttribute(attn_tc_kernel, cudaFuncAttributeMaxDynamicSharedMemorySize, ATTN_SMEM);
    attn_tc_kernel<<<dim3(N_ / 128, B_ * H_), 256, ATTN_SMEM>>>();      // (16, 24)

    cudaFuncSetAttribute(gemm_proj_tc, cudaFuncAttributeMaxDynamicSharedMemorySize, gemm_smem);
    gemm_proj_tc<<<dim3(DIM_ / 128, M1 / 128), 256, gemm_smem>>>(out);  // (6, 32)
}

// round 11
// speedup vs baseline: 4.6100x; 1.1112x over previous
#include <cuda_runtime.h>
#include <cuda_fp16.h>
#include <cstdint>

#define B_   2
#define N_   2048
#define DIM_ 768
#define H_   12
#define DH_  64
#define M1   (B_*N_)     // 4096
#define NC1  (3*DIM_)    // 2304
#define KH2  768         // u32 (pair) count per GEMM row
#define PITCHB 3072      // bytes per GEMM row

// ---------------- device globals ----------------
__device__ uint32_t g_xl[(long)M1*KH2];      // x limbs interleaved (h,l)
__device__ uint32_t g_wd[(long)NC1*KH2];     // wqkv dup pairs (w,w)
__device__ uint32_t g_pd[(long)DIM_*KH2];    // wp dup pairs (w,w)
__device__ uint32_t g_zl[(long)M1*KH2];      // z limbs interleaved (attention out)
__device__ __half   g_qh[(long)B_*H_*N_*DH_];   // q single-limb [bh][n][64]
__device__ __half   g_kh[(long)B_*H_*N_*DH_];   // k single-limb [bh][m][64]
__device__ __half   g_vt[(long)B_*H_*DH_*N_];   // v^T single-limb [bh][e][m]
__device__ float    g_bq[NC1];
__device__ float    g_bp2[DIM_];

// ---------------- quantizers ----------------
__device__ __forceinline__ float qround8(float x) {        // round-half-even to 2^-8
    float t = __fmaf_rn(x, 256.f, 12582912.f);
    return (t - 12582912.f) * 0.00390625f;
}
__device__ __forceinline__ float q16_8c(float x) {         // with clamp (z saturates)
    float t = __fmaf_rn(x, 256.f, 12582912.f);
    float y = t - 12582912.f;
    y = fminf(fmaxf(y, -32768.f), 32767.f);
    return y * 0.00390625f;
}
__device__ __forceinline__ float q32_16(float x) {
    float t = __fmaf_rn(x, 65536.f, 12582912.f);
    return (t - 12582912.f) * 1.52587890625e-5f;
}
__device__ __forceinline__ uint32_t packu32(__half a, __half b) {
    __half2 t = __halves2half2(a, b);
    return *(uint32_t*)&t;
}

// ---------------- PTX helpers ----------------
__device__ __forceinline__ uint32_t smem_u32(const void* p) {
    uint32_t a;
    asm("{ .reg .u64 t; cvta.to.shared.u64 t, %1; cvt.u32.u64 %0, t; }" : "=r"(a) : "l"(p));
    return a;
}
#define CP_ASYNC16(dst, src) \
    asm volatile("cp.async.cg.shared.global [%0], [%1], 16;" :: "r"(dst), "l"(src) : "memory")
#define CP_COMMIT() asm volatile("cp.async.commit_group;" ::: "memory")
#define CP_WAIT(n)  asm volatile("cp.async.wait_group %0;" :: "n"(n) : "memory")

__device__ __forceinline__ void ldm_x4(uint32_t* r, uint32_t addr) {
    asm volatile("ldmatrix.sync.aligned.m8n8.x4.shared.b16 {%0,%1,%2,%3}, [%4];"
        : "=r"(r[0]), "=r"(r[1]), "=r"(r[2]), "=r"(r[3]) : "r"(addr));
}
__device__ __forceinline__ void mma16816(float* d, const uint32_t* a, const uint32_t* b) {
    asm volatile("mma.sync.aligned.m16n8k16.row.col.f32.f16.f16.f32 "
        "{%0,%1,%2,%3}, {%4,%5,%6,%7}, {%8,%9}, {%0,%1,%2,%3};"
        : "+f"(d[0]), "+f"(d[1]), "+f"(d[2]), "+f"(d[3])
        : "r"(a[0]), "r"(a[1]), "r"(a[2]), "r"(a[3]), "r"(b[0]), "r"(b[1]));
}

// 128B-pitch swizzle: XOR 16B-chunk id with row%8
#define SWZ(row, colb) ((uint32_t)((row)*128 + ((colb) ^ (((row)&7)<<4))))

// ---------------- kernel 1: quantize + limb-split inputs ----------------
__global__ void prep_kernel(const float* __restrict__ x, const float* __restrict__ wqkv,
                            const float* __restrict__ bqkv, const float* __restrict__ wp,
                            const float* __restrict__ bp) {
    long i = (long)blockIdx.x * blockDim.x + threadIdx.x;
    const long NX = (long)M1 * DIM_;
    const long NW = (long)NC1 * DIM_;
    const long NP = (long)DIM_ * DIM_;
    if (i < NX) {
        float v = q32_16(x[i]);
        __half h = __float2half_rn(v);
        __half l = __float2half_rn(v - __half2float(h));
        g_xl[i] = packu32(h, l);
        return;
    }
    i -= NX;
    if (i < NW) {
        __half h = __float2half_rn(qround8(wqkv[i]));   // exact: |w*256| << 2048
        g_wd[i] = packu32(h, h);
        return;
    }
    i -= NW;
    if (i < NP) {
        __half h = __float2half_rn(qround8(wp[i]));
        g_pd[i] = packu32(h, h);
        return;
    }
    i -= NP;
    if (i < NC1) { g_bq[i] = qround8(bqkv[i]); return; }
    i -= NC1;
    if (i < DIM_) g_bp2[i] = qround8(bp[i]);
}

// ---------------- QKV GEMM core: 3-stage single-sync (M=128 tile) ----------------
#define GSTG 32768   // A 16KB + B 16KB per stage
struct AccTile { float a[2][8][4]; };

__device__ __forceinline__ void gemm_issue(uint32_t st, const char* Ab, const char* Bb,
                                           int kbyte, int tid) {
    #pragma unroll
    for (int i = 0; i < 4; i++) {
        int idx = tid + i * 256;
        int row = idx >> 3, c16 = (idx & 7) << 4;
        CP_ASYNC16(st + SWZ(row, c16), Ab + (long)row * PITCHB + kbyte + c16);
    }
    #pragma unroll
    for (int i = 0; i < 4; i++) {
        int idx = tid + i * 256;
        int row = idx >> 3, c16 = (idx & 7) << 4;
        CP_ASYNC16(st + 16384 + SWZ(row, c16), Bb + (long)row * PITCHB + kbyte + c16);
    }
    CP_COMMIT();
}

__device__ __forceinline__ void gemm_compute(uint32_t st, AccTile& acc, int wm, int wn, int lane) {
    const int arow_l = (lane & 7) + ((lane >> 3) & 1) * 8;
    const int achk   = (lane >> 4) * 16;
    const int brow_l = (lane & 7) + (lane >> 4) * 8;
    const int bchk   = ((lane >> 3) & 1) * 16;
    #pragma unroll
    for (int kk = 0; kk < 4; kk++) {
        uint32_t a[2][4];
        #pragma unroll
        for (int f = 0; f < 2; f++)
            ldm_x4(a[f], st + SWZ(wm * 32 + f * 16 + arow_l, kk * 32 + achk));
        #pragma unroll
        for (int g = 0; g < 4; g++) {
            uint32_t b4[4];
            ldm_x4(b4, st + 16384 + SWZ(wn * 64 + g * 16 + brow_l, kk * 32 + bchk));
            #pragma unroll
            for (int f = 0; f < 2; f++) {
                mma16816(acc.a[f][g * 2 + 0], a[f], b4 + 0);
                mma16816(acc.a[f][g * 2 + 1], a[f], b4 + 2);
            }
        }
    }
}

__device__ __forceinline__ void gemm_main(const char* Ab, const char* Bb,
                                          AccTile& acc, char* smem, int tid) {
    uint32_t sb = smem_u32(smem);
    const int lane = tid & 31, wid = tid >> 5;
    const int wm = wid & 3, wn = wid >> 2;
    #pragma unroll
    for (int f = 0; f < 2; f++)
        #pragma unroll
        for (int j = 0; j < 8; j++)
            #pragma unroll
            for (int e = 0; e < 4; e++) acc.a[f][j][e] = 0.f;

    gemm_issue(sb + 0 * GSTG, Ab, Bb, 0, tid);
    gemm_issue(sb + 1 * GSTG, Ab, Bb, 128, tid);
    #pragma unroll 1
    for (int g = 0; g < 24; g++) {
        if (g + 2 < 24) { CP_WAIT(1); } else { CP_WAIT(0); }
        __syncthreads();      // stage g ready; all warps done with stage g-1
        if (g + 2 < 24)
            gemm_issue(sb + (uint32_t)((g + 2) % 3) * GSTG, Ab, Bb, (g + 2) * 128, tid);
        gemm_compute(sb + (uint32_t)(g % 3) * GSTG, acc, wm, wn, lane);
    }
}

// ---------------- kernel 2: QKV projection + single-limb q/k/v epilogue ----------------
__global__ void __launch_bounds__(256, 2) gemm_qkv_tc() {
    extern __shared__ char smem[];
    const int tid = threadIdx.x;
    const int m0 = blockIdx.y * 128;
    const int n0 = blockIdx.x * 128;
    AccTile acc;
    gemm_main((const char*)g_xl + (long)m0 * PITCHB,
              (const char*)g_wd + (long)n0 * PITCHB, acc, smem, tid);

    const int wid = tid >> 5, lane = tid & 31;
    const int wm = wid & 3, wn = wid >> 2;
    const int rb = m0 + wm * 32 + (lane >> 2);
    const int cb = n0 + wn * 64 + (lane & 3) * 2;
    #pragma unroll
    for (int f = 0; f < 2; f++) {
        #pragma unroll
        for (int j = 0; j < 8; j++) {
            int nb = cb + j * 8;                 // even
            float b0 = g_bq[nb], b1 = g_bq[nb + 1];
            int h = nb / 192;
            int rr = nb - h * 192;
            int seg = rr >> 6, e = rr & 63;      // e even
            #pragma unroll
            for (int rs = 0; rs < 2; rs++) {
                int m = rb + f * 16 + rs * 8;
                int bi = m >> 11, nr = m & 2047;
                long bh = bi * H_ + h;
                __half h0 = __float2half_rn(qround8(acc.a[f][j][rs * 2 + 0] + b0));
                __half h1 = __float2half_rn(qround8(acc.a[f][j][rs * 2 + 1] + b1));
                if (seg == 0) {
                    *(uint32_t*)(g_qh + (bh * N_ + nr) * DH_ + e) = packu32(h0, h1);
                } else if (seg == 1) {
                    *(uint32_t*)(g_kh + (bh * N_ + nr) * DH_ + e) = packu32(h0, h1);
                } else {
                    g_vt[(bh * DH_ + e) * N_ + nr] = h0;
                    g_vt[(bh * DH_ + e + 1) * N_ + nr] = h1;
                }
            }
        }
    }
}

// ---------------- kernel 4: output projection, M=64 tile, 4-stage ----------------
#define PSTG 24576   // A 8KB + B 16KB per stage

__device__ __forceinline__ void proj_issue(uint32_t st, const char* Ab, const char* Bb,
                                           int kbyte, int tid) {
    #pragma unroll
    for (int i = 0; i < 2; i++) {
        int idx = tid + i * 256;
        int row = idx >> 3, c16 = (idx & 7) << 4;
        CP_ASYNC16(st + SWZ(row, c16), Ab + (long)row * PITCHB + kbyte + c16);
    }
    #pragma unroll
    for (int i = 0; i < 4; i++) {
        int idx = tid + i * 256;
        int row = idx >> 3, c16 = (idx & 7) << 4;
        CP_ASYNC16(st + 8192 + SWZ(row, c16), Bb + (long)row * PITCHB + kbyte + c16);
    }
    CP_COMMIT();
}

__global__ void __launch_bounds__(256, 2) gemm_proj_tc(float* __restrict__ out) {
    extern __shared__ char smem[];
    const uint32_t sb = smem_u32(smem);
    const int tid = threadIdx.x, lane = tid & 31, wid = tid >> 5;
    const int wm = wid & 1, wn = wid >> 1;       // 2 m-groups x 4 n-groups, warp tile 32x32
    const int m0 = blockIdx.y * 64;
    const int n0 = blockIdx.x * 128;
    const char* Ab = (const char*)g_zl + (long)m0 * PITCHB;
    const char* Bb = (const char*)g_pd + (long)n0 * PITCHB;

    const int arow_l = (lane & 7) + ((lane >> 3) & 1) * 8;
    const int achk   = (lane >> 4) * 16;
    const int brow_l = (lane & 7) + (lane >> 4) * 8;
    const int bchk   = ((lane >> 3) & 1) * 16;

    float acc[2][4][4];
    #pragma unroll
    for (int f = 0; f < 2; f++)
        #pragma unroll
        for (int j = 0; j < 4; j++)
            #pragma unroll
            for (int e = 0; e < 4; e++) acc[f][j][e] = 0.f;

    proj_issue(sb + 0 * PSTG, Ab, Bb, 0, tid);
    proj_issue(sb + 1 * PSTG, Ab, Bb, 128, tid);
    proj_issue(sb + 2 * PSTG, Ab, Bb, 256, tid);
    #pragma unroll 1
    for (int g = 0; g < 24; g++) {
        if (g + 3 < 24) { CP_WAIT(2); } else { CP_WAIT(0); }
        __syncthreads();
        if (g + 3 < 24)
            proj_issue(sb + (uint32_t)((g + 3) & 3) * PSTG, Ab, Bb, (g + 3) * 128, tid);
        uint32_t st = sb + (uint32_t)(g & 3) * PSTG;
        #pragma unroll
        for (int kk = 0; kk < 4; kk++) {
            uint32_t a[2][4];
            #pragma unroll
            for (int f = 0; f < 2; f++)
                ldm_x4(a[f], st + SWZ(wm * 32 + f * 16 + arow_l, kk * 32 + achk));
            #pragma unroll
            for (int gg = 0; gg < 2; gg++) {
                uint32_t b4[4];
                ldm_x4(b4, st + 8192 + SWZ(wn * 32 + gg * 16 + brow_l, kk * 32 + bchk));
                #pragma unroll
                for (int f = 0; f < 2; f++) {
                    mma16816(acc[f][gg * 2 + 0], a[f], b4 + 0);
                    mma16816(acc[f][gg * 2 + 1], a[f], b4 + 2);
                }
            }
        }
    }

    const int rb = m0 + wm * 32 + (lane >> 2);
    const int cb = n0 + wn * 32 + (lane & 3) * 2;
    #pragma unroll
    for (int f = 0; f < 2; f++)
        #pragma unroll
        for (int j = 0; j < 4; j++)
            #pragma unroll
            for (int cs = 0; cs < 2; cs++) {
                int n = cb + j * 8 + cs;
                float bias = g_bp2[n];
                #pragma unroll
                for (int rs = 0; rs < 2; rs++) {
                    int m = rb + f * 16 + rs * 8;
                    out[(long)m * DIM_ + n] = qround8(acc[f][j][rs * 2 + cs] + bias);
                }
            }
}

// ---------------- kernel 3: single-limb flash attention, 3-stage KV ring ----------------
// smem: Q [128][64h]=16K | KV 3 stages x (K 8K + V 8K)=48K | Sh 16K | Sl 16K  = 96KB
#define AQ    0u
#define AKV   16384u
#define ASTG  16384u
#define ASH   65536u
#define ASL   81920u
#define ATTN_SMEM 98304

__device__ __forceinline__ void attn_issue(uint32_t stage_base,
        const char* khb, const char* vtb, int kb, int tid) {
    #pragma unroll
    for (int i = 0; i < 2; i++) {
        int idx = tid + i * 256;
        int row = idx >> 3, c16 = (idx & 7) << 4;
        CP_ASYNC16(stage_base + SWZ(row, c16), khb + (long)(kb + row) * 128 + c16);
    }
    #pragma unroll
    for (int i = 0; i < 2; i++) {
        int idx = tid + i * 256;
        int row = idx >> 3, c16 = (idx & 7) << 4;
        CP_ASYNC16(stage_base + 8192 + SWZ(row, c16), vtb + (long)row * (N_ * 2) + kb * 2 + c16);
    }
    CP_COMMIT();
}

__global__ void __launch_bounds__(256, 2) attn_tc_kernel() {
    extern __shared__ char smem[];
    const uint32_t sb = smem_u32(smem);
    const int tid = threadIdx.x;
    const int lane = tid & 31, wid = tid >> 5;
    const int wm = wid & 3, wn = wid >> 2;   // wm: q-row group of 32; wn: col group
    const int bh = blockIdx.y;
    const int q0 = blockIdx.x * 128;

    const char* qhb = (const char*)(g_qh + ((long)bh * N_ + q0) * DH_);
    const char* khb = (const char*)(g_kh + (long)bh * N_ * DH_);
    const char* vtb = (const char*)(g_vt + (long)bh * DH_ * N_);

    // prologue: Q tile (folded into stage-0's group) + stages 0,1
    #pragma unroll
    for (int i = 0; i < 4; i++) {
        int idx = tid + i * 256;
        int row = idx >> 3, c16 = (idx & 7) << 4;
        CP_ASYNC16(sb + AQ + SWZ(row, c16), qhb + (long)row * 128 + c16);
    }
    attn_issue(sb + AKV + 0 * ASTG, khb, vtb, 0, tid);
    attn_issue(sb + AKV + 1 * ASTG, khb, vtb, 64, tid);

    const int arow_l = (lane & 7) + ((lane >> 3) & 1) * 8;
    const int achk   = (lane >> 4) * 16;
    const int brow_l = (lane & 7) + (lane >> 4) * 8;
    const int bchk   = ((lane >> 3) & 1) * 16;
    const int qr     = lane >> 2;
    const int qc     = (lane & 3) * 2;

    uint32_t qfrag[4][2][4];   // Q fragments, loop-invariant (loaded at it==0)
    float zacc[2][4][4];
    #pragma unroll
    for (int f = 0; f < 2; f++)
        #pragma unroll
        for (int j = 0; j < 4; j++)
            #pragma unroll
            for (int e = 0; e < 4; e++) zacc[f][j][e] = 0.f;

    #pragma unroll 1
    for (int it = 0; it < 32; it++) {
        if (it + 2 < 32) { CP_WAIT(1); } else { CP_WAIT(0); }
        __syncthreads();    // stage it ready; all warps done with stage it-1
        if (it + 2 < 32)
            attn_issue(sb + AKV + (uint32_t)((it + 2) % 3) * ASTG, khb, vtb, (it + 2) * 64, tid);
        const uint32_t sK = sb + AKV + (uint32_t)(it % 3) * ASTG;
        const uint32_t sV = sK + 8192u;

        if (it == 0) {
            #pragma unroll
            for (int kk = 0; kk < 4; kk++)
                #pragma unroll
                for (int f = 0; f < 2; f++)
                    ldm_x4(qfrag[kk][f], sb + AQ + SWZ(wm * 32 + f * 16 + arow_l, kk * 32 + achk));
        }

        // ---- phase 1: s[128 x 64] = q x k^T (Q frags in regs; B-only LDSM) ----
        float sacc[2][4][4];
        #pragma unroll
        for (int f = 0; f < 2; f++)
            #pragma unroll
            for (int j = 0; j < 4; j++)
                #pragma unroll
                for (int e = 0; e < 4; e++) sacc[f][j][e] = 0.f;
        #pragma unroll
        for (int kk = 0; kk < 4; kk++) {
            #pragma unroll
            for (int g = 0; g < 2; g++) {
                uint32_t b4[4];
                ldm_x4(b4, sK + SWZ(wn * 32 + g * 16 + brow_l, kk * 32 + bchk));
                #pragma unroll
                for (int f = 0; f < 2; f++) {
                    mma16816(sacc[f][g * 2 + 0], qfrag[kk][f], b4 + 0);
                    mma16816(sacc[f][g * 2 + 1], qfrag[kk][f], b4 + 2);
                }
            }
        }
        // quantize s -> 2 limb planes, packed u32 stores (adjacent cols qc,qc+1)
        #pragma unroll
        for (int f = 0; f < 2; f++)
            #pragma unroll
            for (int j = 0; j < 4; j++)
                #pragma unroll
                for (int rs = 0; rs < 2; rs++) {
                    int row = wm * 32 + f * 16 + qr + rs * 8;
                    int colb = (wn * 32 + j * 8 + qc) * 2;   // 4B aligned
                    float s0 = qround8(sacc[f][j][rs * 2 + 0]);
                    float s1 = qround8(sacc[f][j][rs * 2 + 1]);
                    __half h0 = __float2half_rn(s0);
                    __half h1 = __float2half_rn(s1);
                    __half l0 = __float2half_rn(s0 - __half2float(h0));
                    __half l1 = __float2half_rn(s1 - __half2float(h1));
                    *(uint32_t*)(smem + ASH + SWZ(row, colb)) = packu32(h0, h1);
                    *(uint32_t*)(smem + ASL + SWZ(row, colb)) = packu32(l0, l1);
                }
        __syncthreads();

        // ---- phase 2: z += s x v; V frags shared across both s-limb planes ----
        #pragma unroll
        for (int kk = 0; kk < 4; kk++) {
            uint32_t bv[2][4];
            #pragma unroll
            for (int g = 0; g < 2; g++)
                ldm_x4(bv[g], sV + SWZ(wn * 32 + g * 16 + brow_l, kk * 32 + bchk));
            #pragma unroll
            for (int plane = 0; plane < 2; plane++) {
                uint32_t sp = sb + (plane ? ASL : ASH);
                uint32_t a[2][4];
                #pragma unroll
                for (int f = 0; f < 2; f++)
                    ldm_x4(a[f], sp + SWZ(wm * 32 + f * 16 + arow_l, kk * 32 + achk));
                #pragma unroll
                for (int g = 0; g < 2; g++)
                    #pragma unroll
                    for (int f = 0; f < 2; f++) {
                        mma16816(zacc[f][g * 2 + 0], a[f], bv[g] + 0);
                        mma16816(zacc[f][g * 2 + 1], a[f], bv[g] + 2);
                    }
            }
        }
    }

    // epilogue: quantize z (clamped), limb-split, interleaved layout for proj
    const int b = bh / H_, h = bh - b * H_;
    #pragma unroll
    for (int f = 0; f < 2; f++)
        #pragma unroll
        for (int j = 0; j < 4; j++)
            #pragma unroll
            for (int rs = 0; rs < 2; rs++)
                #pragma unroll
                for (int cs = 0; cs < 2; cs++) {
                    int n = q0 + wm * 32 + f * 16 + qr + rs * 8;
                    int e = wn * 32 + j * 8 + qc + cs;
                    float zq = q16_8c(zacc[f][j][rs * 2 + cs]);
                    __half hh = __float2half_rn(zq);
                    __half ll = __float2half_rn(zq - __half2float(hh));
                    g_zl[((long)(b * N_ + n)) * KH2 + h * DH_ + e] = packu32(hh, ll);
                }
}

// ---------------- launch ----------------
extern "C" void kernel_launch(void* const* d_in, const int* in_sizes, int n_in,
                              void* d_out, int out_size) {
    const float* q_in = (const float*)d_in[0];
    const float* wqkv = (const float*)d_in[1];
    const float* bqkv = (const float*)d_in[2];
    const float* wp   = (const float*)d_in[3];
    const float* bp   = (const float*)d_in[4];
    float* out = (float*)d_out;

    const long total = (long)M1 * DIM_ + (long)NC1 * DIM_ + (long)DIM_ * DIM_ + NC1 + DIM_;
    prep_kernel<<<(unsigned)((total + 255) / 256), 256>>>(q_in, wqkv, bqkv, wp, bp);

    const int gemm_smem = 3 * GSTG;   // 98304 -> 2 CTA/SM
    cudaFuncSetAttribute(gemm_qkv_tc, cudaFuncAttributeMaxDynamicSharedMemorySize, gemm_smem);
    gemm_qkv_tc<<<dim3(NC1 / 128, M1 / 128), 256, gemm_smem>>>();       // (18, 32)

    cudaFuncSetAttribute(attn_tc_kernel, cudaFuncAttributeMaxDynamicSharedMemorySize, ATTN_SMEM);
    attn_tc_kernel<<<dim3(N_ / 128, B_ * H_), 256, ATTN_SMEM>>>();      // (16, 24)

    const int proj_smem = 4 * PSTG;   // 98304 -> 2 CTA/SM
    cudaFuncSetAttribute(gemm_proj_tc, cudaFuncAttributeMaxDynamicSharedMemorySize, proj_smem);
    gemm_proj_tc<<<dim3(DIM_ / 128, M1 / 64), 256, proj_smem>>>(out);   // (6, 64)
}